// round 6
// baseline (speedup 1.0000x reference)
#include <cuda_runtime.h>
#include <math.h>
#include <stdint.h>

// ---------------- problem constants ----------------
#define BB 256
#define SS 128
#define HH 768
#define NHH 8

// ---------------- scratch (static device globals; no runtime alloc) ----------------
__device__ float g_qkv[75497472];      // 32768 * 2304
__device__ float g_abar[BB * HH];
__device__ float g_seqr[BB * HH];
__device__ float g_bufA[BB * 1536];
__device__ float g_bufB[BB * 1536];
__device__ float g_d1o[BB * 384];
__device__ float g_d1pre[BB * 384];
__device__ float g_part[4718592];      // split-K partials: up to 12 * 256 * 1536

// ---------------- tf32 helpers ----------------
__device__ __forceinline__ unsigned f2tf(float x) {
    unsigned r;
    asm("cvt.rna.tf32.f32 %0, %1;" : "=r"(r) : "f"(x));
    return r;
}

// ---------------- shared GEMM core ----------------
// Block tile 128x128, 128 threads (4 warps 2x2), warp tile 64x64 (mt=4, nt=8).
// tf32x2: hi=tf32(x), lo=tf32(x-hi); acc += ah*bl + al*bh + ah*bh.
// smem: Ah[128x36] Al Bh Bl, 73728 B total.
#define SM_AH 0
#define SM_AL 4608
#define SM_BH 9216
#define SM_BL 13824
#define GEMM_SMEM 73728

// load one 128x32 fp32 tile row per thread, split hi/lo, store to smem (padded stride 36)
__device__ __forceinline__ void load_split_row(const float* __restrict__ src,
                                               float* __restrict__ sh, float* __restrict__ sl,
                                               int tid) {
    int base = tid * 36;
#pragma unroll
    for (int i = 0; i < 8; i++) {
        float4 v = *(const float4*)(src + i * 4);
        float4 h, l;
        h.x = __uint_as_float(f2tf(v.x)); l.x = __uint_as_float(f2tf(v.x - h.x));
        h.y = __uint_as_float(f2tf(v.y)); l.y = __uint_as_float(f2tf(v.y - h.y));
        h.z = __uint_as_float(f2tf(v.z)); l.z = __uint_as_float(f2tf(v.z - h.z));
        h.w = __uint_as_float(f2tf(v.w)); l.w = __uint_as_float(f2tf(v.w - h.w));
        *(float4*)(&sh[base + i * 4]) = h;
        *(float4*)(&sl[base + i * 4]) = l;
    }
}

// one 32-wide K-tile of mma work for this warp
__device__ __forceinline__ void mma_ktile(float acc[4][8][4], const float* __restrict__ sm,
                                          int wm, int wn, int g, int t) {
    const float* Ah = sm + SM_AH;
    const float* Al = sm + SM_AL;
    const float* Bh = sm + SM_BH;
    const float* Bl = sm + SM_BL;
#pragma unroll
    for (int ks = 0; ks < 4; ks++) {
        int c0 = ks * 8 + t;
        unsigned bhf[8][2], blf[8][2];
#pragma unroll
        for (int nt = 0; nt < 8; nt++) {
            int n0 = (wn * 64 + nt * 8 + g) * 36 + c0;
            bhf[nt][0] = __float_as_uint(Bh[n0]);
            bhf[nt][1] = __float_as_uint(Bh[n0 + 4]);
            blf[nt][0] = __float_as_uint(Bl[n0]);
            blf[nt][1] = __float_as_uint(Bl[n0 + 4]);
        }
#pragma unroll
        for (int mt = 0; mt < 4; mt++) {
            int r0 = (wm * 64 + mt * 16 + g) * 36 + c0;
            unsigned ah[4], al[4];
            ah[0] = __float_as_uint(Ah[r0]);
            ah[1] = __float_as_uint(Ah[r0 + 288]);
            ah[2] = __float_as_uint(Ah[r0 + 4]);
            ah[3] = __float_as_uint(Ah[r0 + 292]);
            al[0] = __float_as_uint(Al[r0]);
            al[1] = __float_as_uint(Al[r0 + 288]);
            al[2] = __float_as_uint(Al[r0 + 4]);
            al[3] = __float_as_uint(Al[r0 + 292]);
#pragma unroll
            for (int nt = 0; nt < 8; nt++) {
                asm("mma.sync.aligned.m16n8k8.row.col.f32.tf32.tf32.f32 "
                    "{%0,%1,%2,%3},{%4,%5,%6,%7},{%8,%9},{%0,%1,%2,%3};"
                    : "+f"(acc[mt][nt][0]), "+f"(acc[mt][nt][1]),
                      "+f"(acc[mt][nt][2]), "+f"(acc[mt][nt][3])
                    : "r"(ah[0]), "r"(ah[1]), "r"(ah[2]), "r"(ah[3]),
                      "r"(blf[nt][0]), "r"(blf[nt][1]));
                asm("mma.sync.aligned.m16n8k8.row.col.f32.tf32.tf32.f32 "
                    "{%0,%1,%2,%3},{%4,%5,%6,%7},{%8,%9},{%0,%1,%2,%3};"
                    : "+f"(acc[mt][nt][0]), "+f"(acc[mt][nt][1]),
                      "+f"(acc[mt][nt][2]), "+f"(acc[mt][nt][3])
                    : "r"(al[0]), "r"(al[1]), "r"(al[2]), "r"(al[3]),
                      "r"(bhf[nt][0]), "r"(bhf[nt][1]));
                asm("mma.sync.aligned.m16n8k8.row.col.f32.tf32.tf32.f32 "
                    "{%0,%1,%2,%3},{%4,%5,%6,%7},{%8,%9},{%0,%1,%2,%3};"
                    : "+f"(acc[mt][nt][0]), "+f"(acc[mt][nt][1]),
                      "+f"(acc[mt][nt][2]), "+f"(acc[mt][nt][3])
                    : "r"(ah[0]), "r"(ah[1]), "r"(ah[2]), "r"(ah[3]),
                      "r"(bhf[nt][0]), "r"(bhf[nt][1]));
            }
        }
    }
}

// ---------------- generic tf32x2 GEMM:  C[m,n] = sum_k A[m,k] * W[n,k] ----------------
// z-batch: offA = (z/zdiv)*sA1 + (z%zdiv)*sA2 (same for W); offC = z*sC.
__global__ void __launch_bounds__(128, 2) gemm_tf32x2_k(
    const float* __restrict__ A, int lda, long sA1, long sA2,
    const float* __restrict__ W, int ldw, long sW1, long sW2,
    const float* __restrict__ bias, float* __restrict__ C, int ldc, long sC,
    int K, int zdiv)
{
    extern __shared__ float sm[];
    int z = blockIdx.z;
    const float* Ab = A + (long)(z / zdiv) * sA1 + (long)(z % zdiv) * sA2 + (long)blockIdx.y * 128 * lda;
    const float* Wb = W + (long)(z / zdiv) * sW1 + (long)(z % zdiv) * sW2 + (long)blockIdx.x * 128 * ldw;
    float* Cb = C + (long)z * sC + (long)blockIdx.y * 128 * ldc + blockIdx.x * 128;

    int tid = threadIdx.x, warp = tid >> 5, lane = tid & 31;
    int wm = warp >> 1, wn = warp & 1, g = lane >> 2, t = lane & 3;

    float acc[4][8][4];
#pragma unroll
    for (int i = 0; i < 4; i++)
#pragma unroll
        for (int j = 0; j < 8; j++)
#pragma unroll
            for (int e = 0; e < 4; e++) acc[i][j][e] = 0.0f;

    const float* arow = Ab + (long)tid * lda;
    const float* wrow = Wb + (long)tid * ldw;

    for (int k0 = 0; k0 < K; k0 += 32) {
        load_split_row(arow + k0, sm + SM_AH, sm + SM_AL, tid);
        load_split_row(wrow + k0, sm + SM_BH, sm + SM_BL, tid);
        __syncthreads();
        mma_ktile(acc, sm, wm, wn, g, t);
        __syncthreads();
    }

    // epilogue
#pragma unroll
    for (int mt = 0; mt < 4; mt++) {
        int r0 = wm * 64 + mt * 16 + g;
#pragma unroll
        for (int nt = 0; nt < 8; nt++) {
            int c = wn * 64 + nt * 8 + 2 * t;
            float b0 = 0.f, b1 = 0.f;
            if (bias) { b0 = bias[blockIdx.x * 128 + c]; b1 = bias[blockIdx.x * 128 + c + 1]; }
            float* p0 = Cb + (long)r0 * ldc + c;
            float* p1 = Cb + (long)(r0 + 8) * ldc + c;
            p0[0] = acc[mt][nt][0] + b0; p0[1] = acc[mt][nt][1] + b1;
            p1[0] = acc[mt][nt][2] + b0; p1[1] = acc[mt][nt][3] + b1;
        }
    }
}

// ---------------- fused attention per head: scores + softmax colmean + GEMV ----------------
// block = one (b,h): scores = q @ k^T (tf32x2), softmax rows, column mean, * v -> abar
__global__ void __launch_bounds__(128, 2) attn_fused_k(
    const float* __restrict__ qkv, float* __restrict__ abar)
{
    extern __shared__ float sm[];
    int bhid = blockIdx.x;
    int b = bhid >> 3, h = bhid & 7;
    const float* base = qkv + (long)b * SS * 2304 + h * 96;
    const float* Ab = base;          // q rows
    const float* Wb = base + 768;    // k rows

    int tid = threadIdx.x, warp = tid >> 5, lane = tid & 31;
    int wm = warp >> 1, wn = warp & 1, g = lane >> 2, t = lane & 3;

    float acc[4][8][4];
#pragma unroll
    for (int i = 0; i < 4; i++)
#pragma unroll
        for (int j = 0; j < 8; j++)
#pragma unroll
            for (int e = 0; e < 4; e++) acc[i][j][e] = 0.0f;

    const float* arow = Ab + (long)tid * 2304;
    const float* wrow = Wb + (long)tid * 2304;

#pragma unroll
    for (int k0 = 0; k0 < 96; k0 += 32) {
        load_split_row(arow + k0, sm + SM_AH, sm + SM_AL, tid);
        load_split_row(wrow + k0, sm + SM_BH, sm + SM_BL, tid);
        __syncthreads();
        mma_ktile(acc, sm, wm, wn, g, t);
        __syncthreads();
    }

    // scores (scaled) -> smem, stride 129 to avoid bank conflicts
    const float scale = 0.10206207261596577f;   // 1/sqrt(96)
    float* sc = sm;                // 128*129 floats = 66048 B
    float* wa = sm + 16512;        // 4*128 floats
#pragma unroll
    for (int mt = 0; mt < 4; mt++) {
        int r0 = wm * 64 + mt * 16 + g;
#pragma unroll
        for (int nt = 0; nt < 8; nt++) {
            int c = wn * 64 + nt * 8 + 2 * t;
            sc[r0 * 129 + c]       = acc[mt][nt][0] * scale;
            sc[r0 * 129 + c + 1]   = acc[mt][nt][1] * scale;
            sc[(r0 + 8) * 129 + c]     = acc[mt][nt][2] * scale;
            sc[(r0 + 8) * 129 + c + 1] = acc[mt][nt][3] * scale;
        }
    }
    __syncthreads();

    // per-row softmax, accumulate column sums (per-warp partials)
#pragma unroll
    for (int j = 0; j < 4; j++) wa[warp * 128 + lane + 32 * j] = 0.0f;
    __syncwarp();

    for (int s = warp; s < 128; s += 4) {
        float x0 = sc[s * 129 + lane];
        float x1 = sc[s * 129 + lane + 32];
        float x2 = sc[s * 129 + lane + 64];
        float x3 = sc[s * 129 + lane + 96];
        float m = fmaxf(fmaxf(x0, x1), fmaxf(x2, x3));
#pragma unroll
        for (int o = 16; o; o >>= 1) m = fmaxf(m, __shfl_xor_sync(0xffffffffu, m, o));
        float e0 = expf(x0 - m), e1 = expf(x1 - m), e2 = expf(x2 - m), e3 = expf(x3 - m);
        float smm = e0 + e1 + e2 + e3;
#pragma unroll
        for (int o = 16; o; o >>= 1) smm += __shfl_xor_sync(0xffffffffu, smm, o);
        float inv = 1.0f / smm;
        wa[warp * 128 + lane]      += e0 * inv;
        wa[warp * 128 + lane + 32] += e1 * inv;
        wa[warp * 128 + lane + 64] += e2 * inv;
        wa[warp * 128 + lane + 96] += e3 * inv;
    }
    __syncthreads();
    if (warp == 0) {
#pragma unroll
        for (int j = 0; j < 4; j++) {
            int c = lane + 32 * j;
            wa[c] = wa[c] + wa[128 + c] + wa[256 + c] + wa[384 + c];
        }
    }
    __syncthreads();

    // abar[b, h*96+d] = (1/S) * sum_k wa[k] * v[k,d]
    if (tid < 96) {
        const float* v = qkv + (long)b * SS * 2304 + 1536 + h * 96 + tid;
        float a = 0.0f;
#pragma unroll 8
        for (int k = 0; k < 128; k++) a = fmaf(wa[k], v[(long)k * 2304], a);
        abar[b * HH + h * 96 + tid] = a * (1.0f / 128.0f);
    }
}

// ---------------- split-K reduction: C[i] = sum_z part[z][i] + bias[i % N] ----------------
__global__ void reduce_k(const float* __restrict__ part, int Z, long stride,
                         const float* __restrict__ bias, int N,
                         float* __restrict__ C, int total)
{
    int i = blockIdx.x * blockDim.x + threadIdx.x;
    if (i < total) {
        float s = 0.f;
        for (int zz = 0; zz < Z; zz++) s += part[(long)zz * stride + i];
        C[i] = s + bias[i % N];
    }
}

// ---------------- fused LayerNorm + exact GELU ----------------
__global__ void ln_gelu_k(const float* __restrict__ in, const float* __restrict__ gm,
                          const float* __restrict__ be, float* __restrict__ out, int N)
{
    int row = blockIdx.x;
    const float* x = in + (long)row * N;
    float* y = out + (long)row * N;
    int tid = threadIdx.x, warp = tid >> 5, lane = tid & 31;

    float s = 0.f, s2 = 0.f;
    for (int i = tid; i < N; i += blockDim.x) { float v = x[i]; s += v; s2 += v * v; }
#pragma unroll
    for (int o = 16; o; o >>= 1) { s += __shfl_xor_sync(0xffffffffu, s, o); s2 += __shfl_xor_sync(0xffffffffu, s2, o); }
    __shared__ float rs[8], rs2[8], sm_mean, sm_rstd;
    if (lane == 0) { rs[warp] = s; rs2[warp] = s2; }
    __syncthreads();
    if (tid == 0) {
        float S = 0.f, S2 = 0.f;
        for (int w = 0; w < 8; w++) { S += rs[w]; S2 += rs2[w]; }
        float mean = S / N;
        float var = S2 / N - mean * mean;
        sm_mean = mean;
        sm_rstd = rsqrtf(var + 1e-5f);
    }
    __syncthreads();
    float mean = sm_mean, rstd = sm_rstd;
    for (int i = tid; i < N; i += blockDim.x) {
        float v = (x[i] - mean) * rstd * gm[i] + be[i];
        y[i] = 0.5f * v * (1.0f + erff(v * 0.70710678118654752f));
    }
}

// ---------------- warp dot helper ----------------
__device__ __forceinline__ float warp_dot(const float* a, const float* b, int n, int lane)
{
    float s = 0.f;
    for (int i = lane; i < n; i += 32) s = fmaf(a[i], b[i], s);
#pragma unroll
    for (int o = 16; o; o >>= 1) s += __shfl_xor_sync(0xffffffffu, s, o);
    return s;
}

// ---------------- small 5-way head (domain logits) ----------------
__global__ void head5_kernel(const float* __restrict__ in, int Kin,
                             const float* __restrict__ w, const float* __restrict__ bias,
                             float* __restrict__ out)
{
    int b = blockIdx.x, warp = threadIdx.x >> 5, lane = threadIdx.x & 31;
    if (warp < 5) {
        float s = warp_dot(in + (long)b * Kin, w + (long)warp * Kin, Kin, lane);
        if (lane == 0) out[b * 5 + warp] = s + bias[warp];
    }
}

// ---------------- gating softmax + top-2 + expert mix ----------------
__global__ void gate_kernel(const float* __restrict__ r1o,
                            const float* __restrict__ w_r2, const float* __restrict__ b_r2,
                            const float* __restrict__ hs,
                            const float* __restrict__ w_e, const float* __restrict__ b_e,
                            float* __restrict__ out)
{
    __shared__ float gl[5], ae[10];
    int b = blockIdx.x, tid = threadIdx.x, warp = tid >> 5, lane = tid & 31;

    if (warp < 5) {
        float s = warp_dot(r1o + (long)b * 384, w_r2 + (long)warp * 384, 384, lane);
        if (lane == 0) gl[warp] = s + b_r2[warp];
    }
    const float* cls = hs + (long)b * SS * HH;
    for (int idx = warp; idx < 10; idx += 8) {
        float s = warp_dot(cls, w_e + (long)idx * HH, HH, lane);
        if (lane == 0) ae[idx] = s + b_e[idx];
    }
    __syncthreads();

    if (tid == 0) {
        float m = gl[0];
        for (int j = 1; j < 5; j++) m = fmaxf(m, gl[j]);
        float e[5], sum = 0.f;
        for (int j = 0; j < 5; j++) { e[j] = expf(gl[j] - m); sum += e[j]; }
        float p[5];
        for (int j = 0; j < 5; j++) { p[j] = e[j] / sum; out[512 + b * 5 + j] = p[j]; }
        int i1 = 0;
        for (int j = 1; j < 5; j++) if (p[j] > p[i1]) i1 = j;
        int i2 = -1;
        for (int j = 0; j < 5; j++) if (j != i1 && (i2 < 0 || p[j] > p[i2])) i2 = j;
        float ps = p[i1] + p[i2];
        float w1 = p[i1] / ps, w2 = p[i2] / ps;
        for (int ee = 0; ee < 5; ee++) {
            bool sel = (ee == i1) || (ee == i2);
            out[1792 + b * 10 + ee * 2 + 0] = sel ? ae[ee * 2 + 0] : 0.0f;
            out[1792 + b * 10 + ee * 2 + 1] = sel ? ae[ee * 2 + 1] : 0.0f;
        }
        out[b * 2 + 0] = w1 * ae[i1 * 2 + 0] + w2 * ae[i2 * 2 + 0];
        out[b * 2 + 1] = w1 * ae[i1 * 2 + 1] + w2 * ae[i2 * 2 + 1];
    }
}

// ---------------- host launcher ----------------
extern "C" void kernel_launch(void* const* d_in, const int* in_sizes, int n_in,
                              void* d_out, int out_size)
{
    const float* hs    = (const float*)d_in[0];
    const float* w_qkv = (const float*)d_in[1];
    const float* b_qkv = (const float*)d_in[2];
    const float* w_out = (const float*)d_in[3];
    const float* b_out = (const float*)d_in[4];
    const float* w_f1  = (const float*)d_in[5];
    const float* b_f1  = (const float*)d_in[6];
    const float* gf1   = (const float*)d_in[7];
    const float* bef1  = (const float*)d_in[8];
    const float* w_f2  = (const float*)d_in[9];
    const float* b_f2  = (const float*)d_in[10];
    const float* gf2   = (const float*)d_in[11];
    const float* bef2  = (const float*)d_in[12];
    const float* w_c   = (const float*)d_in[13];
    const float* b_c   = (const float*)d_in[14];
    const float* gc    = (const float*)d_in[15];
    const float* bec   = (const float*)d_in[16];
    const float* w_r1  = (const float*)d_in[17];
    const float* b_r1  = (const float*)d_in[18];
    const float* gr1   = (const float*)d_in[19];
    const float* ber1  = (const float*)d_in[20];
    const float* w_r2  = (const float*)d_in[21];
    const float* b_r2  = (const float*)d_in[22];
    const float* w_d1  = (const float*)d_in[23];
    const float* b_d1  = (const float*)d_in[24];
    const float* gd1   = (const float*)d_in[25];
    const float* bed1  = (const float*)d_in[26];
    const float* w_d2  = (const float*)d_in[27];
    const float* b_d2  = (const float*)d_in[28];
    const float* w_e   = (const float*)d_in[29];
    const float* b_e   = (const float*)d_in[30];
    float* out = (float*)d_out;

    float *qkv, *abar, *seqr, *bufA, *bufB, *d1o, *d1pre, *part;
    cudaGetSymbolAddress((void**)&qkv,   g_qkv);
    cudaGetSymbolAddress((void**)&abar,  g_abar);
    cudaGetSymbolAddress((void**)&seqr,  g_seqr);
    cudaGetSymbolAddress((void**)&bufA,  g_bufA);
    cudaGetSymbolAddress((void**)&bufB,  g_bufB);
    cudaGetSymbolAddress((void**)&d1o,   g_d1o);
    cudaGetSymbolAddress((void**)&d1pre, g_d1pre);
    cudaGetSymbolAddress((void**)&part,  g_part);

    cudaFuncSetAttribute(gemm_tf32x2_k, cudaFuncAttributeMaxDynamicSharedMemorySize, GEMM_SMEM);
    cudaFuncSetAttribute(attn_fused_k,  cudaFuncAttributeMaxDynamicSharedMemorySize, GEMM_SMEM);

    // split-K GEMM helper for the B=256 chain (Kc=128)
    auto gemmsk = [&](const float* A, int lda, const float* W, const float* bias,
                      float* Cfinal, int N, int K) {
        const int Kc = 128;
        int Z = K / Kc;
        dim3 grid(N / 128, BB / 128, Z);
        gemm_tf32x2_k<<<grid, 128, GEMM_SMEM>>>(
            A, lda, 0, Kc, W, K, 0, Kc, nullptr, part, N, (long)BB * N, Kc, Z);
        int total = BB * N;
        reduce_k<<<(total + 255) / 256, 256>>>(part, Z, (long)BB * N, bias, N, Cfinal, total);
    };

    // --- domain path first (independent; also positions qkv as 6th launch for ncu -s 5) ---
    {
        const int Kc = 128, Z = 6;                  // K=768
        dim3 grid(384 / 128, BB / 128, Z);
        gemm_tf32x2_k<<<grid, 128, GEMM_SMEM>>>(    // launch 1
            hs, SS * HH, 0, Kc, w_d1, HH, 0, Kc, nullptr, part, 384, (long)BB * 384, Kc, Z);
        int half = BB * 384 / 2;                    // 49152 = 128*384 (bias phase preserved)
        reduce_k<<<(half + 255) / 256, 256>>>(part, Z, (long)BB * 384, b_d1, 384, d1pre, half);           // 2
        reduce_k<<<(half + 255) / 256, 256>>>(part + half, Z, (long)BB * 384, b_d1, 384, d1pre + half, half); // 3
    }
    ln_gelu_k<<<BB, 256>>>(d1pre, gd1, bed1, d1o, 384);             // 4
    head5_kernel<<<BB, 160>>>(d1o, 384, w_d2, b_d2, out + 4352);    // 5

    // --- qkv = hs @ w_qkv.T + b_qkv  (M=32768, N=2304, K=768) ---  launch 6 (profiled)
    gemm_tf32x2_k<<<dim3(2304 / 128, 32768 / 128, 1), 128, GEMM_SMEM>>>(
        hs, HH, 0, 0, w_qkv, HH, 0, 0, b_qkv, qkv, 2304, 0, HH, 1);

    // --- fused attention: scores + softmax colmean + GEMV -> abar ---
    attn_fused_k<<<BB * NHH, 128, GEMM_SMEM>>>(qkv, abar);

    // --- seq_repr = abar @ w_out.T + b_out (mean commutes with linear) ---
    gemmsk(abar, HH, w_out, b_out, seqr, HH, HH);

    // --- f1 -> f2 -> ctx -> r1 chain ---
    gemmsk(seqr, HH, w_f1, b_f1, bufA, 1536, HH);
    ln_gelu_k<<<BB, 256>>>(bufA, gf1, bef1, bufB, 1536);

    gemmsk(bufB, 1536, w_f2, b_f2, bufA, 1536, 1536);
    ln_gelu_k<<<BB, 256>>>(bufA, gf2, bef2, bufB, 1536);

    gemmsk(bufB, 1536, w_c, b_c, bufA, HH, 1536);
    ln_gelu_k<<<BB, 256>>>(bufA, gc, bec, bufB, HH);

    gemmsk(bufB, HH, w_r1, b_r1, bufA, 384, HH);
    ln_gelu_k<<<BB, 256>>>(bufA, gr1, ber1, bufB, 384);   // bufB = r1o

    // --- gating softmax + top-2 + expert logits / final logits ---
    gate_kernel<<<BB, 256>>>(bufB, w_r2, b_r2, hs, w_e, b_e, out);

    (void)in_sizes; (void)n_in; (void)out_size;
}

// round 7
// speedup vs baseline: 1.5783x; 1.5783x over previous
#include <cuda_runtime.h>
#include <cuda_bf16.h>
#include <math.h>
#include <stdint.h>

// ---------------- problem constants ----------------
#define BB 256
#define SS 128
#define HH 768
#define NHH 8

// ---------------- scratch (static device globals; no runtime alloc) ----------------
__device__ float g_qkv[75497472];      // 32768 * 2304
__device__ float g_abar[BB * HH];
__device__ float g_seqr[BB * HH];
__device__ float g_bufA[BB * 1536];
__device__ float g_bufB[BB * 1536];
__device__ float g_d1o[BB * 384];
__device__ float g_d1pre[BB * 384];
__device__ float g_part[4718592];      // split-K partials: up to 12 * 256 * 1536

// ---------------- bf16x2 split helpers ----------------
// pack rn-bf16 of (x0,x1) into one word (x0 -> low half = element k, x1 -> high = k+1),
// and the bf16 of the residuals into another word.
__device__ __forceinline__ void split2(float x0, float x1, uint32_t& h, uint32_t& l) {
    asm("cvt.rn.bf16x2.f32 %0, %1, %2;" : "=r"(h) : "f"(x1), "f"(x0));
    __nv_bfloat162 hb = *reinterpret_cast<__nv_bfloat162*>(&h);
    float h0 = __low2float(hb), h1 = __high2float(hb);
    asm("cvt.rn.bf16x2.f32 %0, %1, %2;" : "=r"(l) : "f"(x1 - h1), "f"(x0 - h0));
}

// ---------------- GEMM core (R5 engine shape, bf16x2 numerics) ----------------
// Block tile 128x128, 256 threads (8 warps 2x4), warp tile 64x32 (mt=4, nt=4).
// smem: 4 arrays of 128 rows x 16 words (k-pairs), padded row stride 20 words
// (conflict-free fragment loads: banks (20g+t) mod 32 all distinct).
#define SMW 20
#define OF_AH 0
#define OF_AL 2560
#define OF_BH 5120
#define OF_BL 7680
#define GEMM_SMEM 40960     // 10240 words * 4B

// load 16 floats (half a 32-wide row), split, store 8 hi + 8 lo words
__device__ __forceinline__ void load_split16(const float* __restrict__ src,
                                             uint32_t* __restrict__ sh,
                                             uint32_t* __restrict__ sl, int wbase) {
    uint32_t hw[8], lw[8];
#pragma unroll
    for (int i = 0; i < 4; i++) {
        float4 v = *(const float4*)(src + i * 4);
        split2(v.x, v.y, hw[2 * i], lw[2 * i]);
        split2(v.z, v.w, hw[2 * i + 1], lw[2 * i + 1]);
    }
    *(uint4*)(sh + wbase)     = make_uint4(hw[0], hw[1], hw[2], hw[3]);
    *(uint4*)(sh + wbase + 4) = make_uint4(hw[4], hw[5], hw[6], hw[7]);
    *(uint4*)(sl + wbase)     = make_uint4(lw[0], lw[1], lw[2], lw[3]);
    *(uint4*)(sl + wbase + 4) = make_uint4(lw[4], lw[5], lw[6], lw[7]);
}

#define MMA_BF16(acc, a0, a1, a2, a3, b0, b1) \
    asm("mma.sync.aligned.m16n8k16.row.col.f32.bf16.bf16.f32 " \
        "{%0,%1,%2,%3},{%4,%5,%6,%7},{%8,%9},{%0,%1,%2,%3};" \
        : "+f"((acc)[0]), "+f"((acc)[1]), "+f"((acc)[2]), "+f"((acc)[3]) \
        : "r"(a0), "r"(a1), "r"(a2), "r"(a3), "r"(b0), "r"(b1))

// one 32-wide K-tile of mma work for this warp (2 k16 steps x 3 passes)
__device__ __forceinline__ void mma_ktile(float acc[4][4][4], const uint32_t* __restrict__ sm,
                                          int wm, int wn, int g, int t) {
    const uint32_t* AH = sm + OF_AH;
    const uint32_t* AL = sm + OF_AL;
    const uint32_t* BH = sm + OF_BH;
    const uint32_t* BL = sm + OF_BL;
#pragma unroll
    for (int ks = 0; ks < 2; ks++) {
        int wb = ks * 8 + t;
        uint32_t bh_[4][2], bl_[4][2];
#pragma unroll
        for (int nt = 0; nt < 4; nt++) {
            int n0 = (wn * 32 + nt * 8 + g) * SMW + wb;
            bh_[nt][0] = BH[n0];  bh_[nt][1] = BH[n0 + 4];
            bl_[nt][0] = BL[n0];  bl_[nt][1] = BL[n0 + 4];
        }
#pragma unroll
        for (int mt = 0; mt < 4; mt++) {
            int r0 = (wm * 64 + mt * 16 + g) * SMW + wb;
            int r1 = r0 + 8 * SMW;
            uint32_t ah0 = AH[r0], ah1 = AH[r1], ah2 = AH[r0 + 4], ah3 = AH[r1 + 4];
            uint32_t al0 = AL[r0], al1 = AL[r1], al2 = AL[r0 + 4], al3 = AL[r1 + 4];
#pragma unroll
            for (int nt = 0; nt < 4; nt++) {
                MMA_BF16(acc[mt][nt], ah0, ah1, ah2, ah3, bl_[nt][0], bl_[nt][1]);
                MMA_BF16(acc[mt][nt], al0, al1, al2, al3, bh_[nt][0], bh_[nt][1]);
                MMA_BF16(acc[mt][nt], ah0, ah1, ah2, ah3, bh_[nt][0], bh_[nt][1]);
            }
        }
    }
}

// ---------------- generic bf16x2 GEMM:  C[m,n] = sum_k A[m,k] * W[n,k] ----------------
// z-batch: offA = (z/zdiv)*sA1 + (z%zdiv)*sA2 (same for W); offC = z*sC.
__global__ void __launch_bounds__(256, 2) gemm_bf16x2_k(
    const float* __restrict__ A, int lda, long sA1, long sA2,
    const float* __restrict__ W, int ldw, long sW1, long sW2,
    const float* __restrict__ bias, float* __restrict__ C, int ldc, long sC,
    int K, int zdiv)
{
    extern __shared__ uint32_t sm[];
    int z = blockIdx.z;
    const float* Ab = A + (long)(z / zdiv) * sA1 + (long)(z % zdiv) * sA2 + (long)blockIdx.y * 128 * lda;
    const float* Wb = W + (long)(z / zdiv) * sW1 + (long)(z % zdiv) * sW2 + (long)blockIdx.x * 128 * ldw;
    float* Cb = C + (long)z * sC + (long)blockIdx.y * 128 * ldc + blockIdx.x * 128;

    int tid = threadIdx.x, warp = tid >> 5, lane = tid & 31;
    int wm = warp >> 2, wn = warp & 3, g = lane >> 2, t = lane & 3;

    int lr = tid >> 1, lh = (tid & 1) * 16;
    int wbase = lr * SMW + (tid & 1) * 8;
    const float* arow = Ab + (long)lr * lda + lh;
    const float* wrow = Wb + (long)lr * ldw + lh;

    float acc[4][4][4];
#pragma unroll
    for (int i = 0; i < 4; i++)
#pragma unroll
        for (int j = 0; j < 4; j++)
#pragma unroll
            for (int e = 0; e < 4; e++) acc[i][j][e] = 0.0f;

    for (int k0 = 0; k0 < K; k0 += 32) {
        load_split16(arow + k0, sm + OF_AH, sm + OF_AL, wbase);
        load_split16(wrow + k0, sm + OF_BH, sm + OF_BL, wbase);
        __syncthreads();
        mma_ktile(acc, sm, wm, wn, g, t);
        __syncthreads();
    }

#pragma unroll
    for (int mt = 0; mt < 4; mt++) {
        int r0 = wm * 64 + mt * 16 + g;
#pragma unroll
        for (int nt = 0; nt < 4; nt++) {
            int c = wn * 32 + nt * 8 + 2 * t;
            float b0 = 0.f, b1 = 0.f;
            if (bias) { b0 = bias[blockIdx.x * 128 + c]; b1 = bias[blockIdx.x * 128 + c + 1]; }
            float* p0 = Cb + (long)r0 * ldc + c;
            float* p1 = Cb + (long)(r0 + 8) * ldc + c;
            p0[0] = acc[mt][nt][0] + b0; p0[1] = acc[mt][nt][1] + b1;
            p1[0] = acc[mt][nt][2] + b0; p1[1] = acc[mt][nt][3] + b1;
        }
    }
}

// ---------------- fused attention per head: scores + softmax colmean + GEMV ----------------
// smem: reuse tile region, then scores 128x132 fp32 + wa 8x128
#define ATTN_SMEM ((128 * 132 + 8 * 128) * 4)   // 71680 B > GEMM_SMEM
__global__ void __launch_bounds__(256, 2) attn_fused_k(
    const float* __restrict__ qkv, float* __restrict__ abar)
{
    extern __shared__ uint32_t sm[];
    int bhid = blockIdx.x;
    int b = bhid >> 3, h = bhid & 7;
    const float* base = qkv + (long)b * SS * 2304 + h * 96;

    int tid = threadIdx.x, warp = tid >> 5, lane = tid & 31;
    int wm = warp >> 2, wn = warp & 3, g = lane >> 2, t = lane & 3;

    int lr = tid >> 1, lh = (tid & 1) * 16;
    int wbase = lr * SMW + (tid & 1) * 8;
    const float* arow = base + (long)lr * 2304 + lh;          // q
    const float* wrow = base + 768 + (long)lr * 2304 + lh;    // k

    float acc[4][4][4];
#pragma unroll
    for (int i = 0; i < 4; i++)
#pragma unroll
        for (int j = 0; j < 4; j++)
#pragma unroll
            for (int e = 0; e < 4; e++) acc[i][j][e] = 0.0f;

#pragma unroll
    for (int k0 = 0; k0 < 96; k0 += 32) {
        load_split16(arow + k0, sm + OF_AH, sm + OF_AL, wbase);
        load_split16(wrow + k0, sm + OF_BH, sm + OF_BL, wbase);
        __syncthreads();
        mma_ktile(acc, sm, wm, wn, g, t);
        __syncthreads();
    }

    // scaled scores -> smem (stride 132)
    const float scale = 0.10206207261596577f;   // 1/sqrt(96)
    float* sc = (float*)sm;
    float* wa = (float*)(sm + 128 * 132);
#pragma unroll
    for (int mt = 0; mt < 4; mt++) {
        int r0 = wm * 64 + mt * 16 + g;
#pragma unroll
        for (int nt = 0; nt < 4; nt++) {
            int c = wn * 32 + nt * 8 + 2 * t;
            sc[r0 * 132 + c]           = acc[mt][nt][0] * scale;
            sc[r0 * 132 + c + 1]       = acc[mt][nt][1] * scale;
            sc[(r0 + 8) * 132 + c]     = acc[mt][nt][2] * scale;
            sc[(r0 + 8) * 132 + c + 1] = acc[mt][nt][3] * scale;
        }
    }
    __syncthreads();

    // per-row softmax; accumulate per-warp column sums
#pragma unroll
    for (int j = 0; j < 4; j++) wa[warp * 128 + lane + 32 * j] = 0.0f;
    __syncwarp();

    for (int s = warp; s < 128; s += 8) {
        float x0 = sc[s * 132 + lane];
        float x1 = sc[s * 132 + lane + 32];
        float x2 = sc[s * 132 + lane + 64];
        float x3 = sc[s * 132 + lane + 96];
        float m = fmaxf(fmaxf(x0, x1), fmaxf(x2, x3));
#pragma unroll
        for (int o = 16; o; o >>= 1) m = fmaxf(m, __shfl_xor_sync(0xffffffffu, m, o));
        float e0 = expf(x0 - m), e1 = expf(x1 - m), e2 = expf(x2 - m), e3 = expf(x3 - m);
        float smm = e0 + e1 + e2 + e3;
#pragma unroll
        for (int o = 16; o; o >>= 1) smm += __shfl_xor_sync(0xffffffffu, smm, o);
        float inv = 1.0f / smm;
        wa[warp * 128 + lane]      += e0 * inv;
        wa[warp * 128 + lane + 32] += e1 * inv;
        wa[warp * 128 + lane + 64] += e2 * inv;
        wa[warp * 128 + lane + 96] += e3 * inv;
    }
    __syncthreads();
    if (warp == 0) {
#pragma unroll
        for (int j = 0; j < 4; j++) {
            int c = lane + 32 * j;
            float s = 0.f;
#pragma unroll
            for (int w = 0; w < 8; w++) s += wa[w * 128 + c];
            wa[c] = s;
        }
    }
    __syncthreads();

    if (tid < 96) {
        const float* v = qkv + (long)b * SS * 2304 + 1536 + h * 96 + tid;
        float a = 0.0f;
#pragma unroll 8
        for (int k = 0; k < 128; k++) a = fmaf(wa[k], v[(long)k * 2304], a);
        abar[b * HH + h * 96 + tid] = a * (1.0f / 128.0f);
    }
}

// ---------------- split-K reduction ----------------
__global__ void reduce_k(const float* __restrict__ part, int Z, long stride,
                         const float* __restrict__ bias, int N,
                         float* __restrict__ C, int total)
{
    int i = blockIdx.x * blockDim.x + threadIdx.x;
    if (i < total) {
        float s = 0.f;
        for (int zz = 0; zz < Z; zz++) s += part[(long)zz * stride + i];
        C[i] = s + bias[i % N];
    }
}

// ---------------- fused LayerNorm + exact GELU ----------------
__global__ void ln_gelu_k(const float* __restrict__ in, const float* __restrict__ gm,
                          const float* __restrict__ be, float* __restrict__ out, int N)
{
    int row = blockIdx.x;
    const float* x = in + (long)row * N;
    float* y = out + (long)row * N;
    int tid = threadIdx.x, warp = tid >> 5, lane = tid & 31;

    float s = 0.f, s2 = 0.f;
    for (int i = tid; i < N; i += blockDim.x) { float v = x[i]; s += v; s2 += v * v; }
#pragma unroll
    for (int o = 16; o; o >>= 1) { s += __shfl_xor_sync(0xffffffffu, s, o); s2 += __shfl_xor_sync(0xffffffffu, s2, o); }
    __shared__ float rs[8], rs2[8], sm_mean, sm_rstd;
    if (lane == 0) { rs[warp] = s; rs2[warp] = s2; }
    __syncthreads();
    if (tid == 0) {
        float S = 0.f, S2 = 0.f;
        for (int w = 0; w < 8; w++) { S += rs[w]; S2 += rs2[w]; }
        float mean = S / N;
        float var = S2 / N - mean * mean;
        sm_mean = mean;
        sm_rstd = rsqrtf(var + 1e-5f);
    }
    __syncthreads();
    float mean = sm_mean, rstd = sm_rstd;
    for (int i = tid; i < N; i += blockDim.x) {
        float v = (x[i] - mean) * rstd * gm[i] + be[i];
        y[i] = 0.5f * v * (1.0f + erff(v * 0.70710678118654752f));
    }
}

// ---------------- warp dot helper ----------------
__device__ __forceinline__ float warp_dot(const float* a, const float* b, int n, int lane)
{
    float s = 0.f;
    for (int i = lane; i < n; i += 32) s = fmaf(a[i], b[i], s);
#pragma unroll
    for (int o = 16; o; o >>= 1) s += __shfl_xor_sync(0xffffffffu, s, o);
    return s;
}

// ---------------- small 5-way head (domain logits) ----------------
__global__ void head5_kernel(const float* __restrict__ in, int Kin,
                             const float* __restrict__ w, const float* __restrict__ bias,
                             float* __restrict__ out)
{
    int b = blockIdx.x, warp = threadIdx.x >> 5, lane = threadIdx.x & 31;
    if (warp < 5) {
        float s = warp_dot(in + (long)b * Kin, w + (long)warp * Kin, Kin, lane);
        if (lane == 0) out[b * 5 + warp] = s + bias[warp];
    }
}

// ---------------- gating softmax + top-2 + expert mix ----------------
__global__ void gate_kernel(const float* __restrict__ r1o,
                            const float* __restrict__ w_r2, const float* __restrict__ b_r2,
                            const float* __restrict__ hs,
                            const float* __restrict__ w_e, const float* __restrict__ b_e,
                            float* __restrict__ out)
{
    __shared__ float gl[5], ae[10];
    int b = blockIdx.x, tid = threadIdx.x, warp = tid >> 5, lane = tid & 31;

    if (warp < 5) {
        float s = warp_dot(r1o + (long)b * 384, w_r2 + (long)warp * 384, 384, lane);
        if (lane == 0) gl[warp] = s + b_r2[warp];
    }
    const float* cls = hs + (long)b * SS * HH;
    for (int idx = warp; idx < 10; idx += 8) {
        float s = warp_dot(cls, w_e + (long)idx * HH, HH, lane);
        if (lane == 0) ae[idx] = s + b_e[idx];
    }
    __syncthreads();

    if (tid == 0) {
        float m = gl[0];
        for (int j = 1; j < 5; j++) m = fmaxf(m, gl[j]);
        float e[5], sum = 0.f;
        for (int j = 0; j < 5; j++) { e[j] = expf(gl[j] - m); sum += e[j]; }
        float p[5];
        for (int j = 0; j < 5; j++) { p[j] = e[j] / sum; out[512 + b * 5 + j] = p[j]; }
        int i1 = 0;
        for (int j = 1; j < 5; j++) if (p[j] > p[i1]) i1 = j;
        int i2 = -1;
        for (int j = 0; j < 5; j++) if (j != i1 && (i2 < 0 || p[j] > p[i2])) i2 = j;
        float ps = p[i1] + p[i2];
        float w1 = p[i1] / ps, w2 = p[i2] / ps;
        for (int ee = 0; ee < 5; ee++) {
            bool sel = (ee == i1) || (ee == i2);
            out[1792 + b * 10 + ee * 2 + 0] = sel ? ae[ee * 2 + 0] : 0.0f;
            out[1792 + b * 10 + ee * 2 + 1] = sel ? ae[ee * 2 + 1] : 0.0f;
        }
        out[b * 2 + 0] = w1 * ae[i1 * 2 + 0] + w2 * ae[i2 * 2 + 0];
        out[b * 2 + 1] = w1 * ae[i1 * 2 + 1] + w2 * ae[i2 * 2 + 1];
    }
}

// ---------------- host launcher ----------------
extern "C" void kernel_launch(void* const* d_in, const int* in_sizes, int n_in,
                              void* d_out, int out_size)
{
    const float* hs    = (const float*)d_in[0];
    const float* w_qkv = (const float*)d_in[1];
    const float* b_qkv = (const float*)d_in[2];
    const float* w_out = (const float*)d_in[3];
    const float* b_out = (const float*)d_in[4];
    const float* w_f1  = (const float*)d_in[5];
    const float* b_f1  = (const float*)d_in[6];
    const float* gf1   = (const float*)d_in[7];
    const float* bef1  = (const float*)d_in[8];
    const float* w_f2  = (const float*)d_in[9];
    const float* b_f2  = (const float*)d_in[10];
    const float* gf2   = (const float*)d_in[11];
    const float* bef2  = (const float*)d_in[12];
    const float* w_c   = (const float*)d_in[13];
    const float* b_c   = (const float*)d_in[14];
    const float* gc    = (const float*)d_in[15];
    const float* bec   = (const float*)d_in[16];
    const float* w_r1  = (const float*)d_in[17];
    const float* b_r1  = (const float*)d_in[18];
    const float* gr1   = (const float*)d_in[19];
    const float* ber1  = (const float*)d_in[20];
    const float* w_r2  = (const float*)d_in[21];
    const float* b_r2  = (const float*)d_in[22];
    const float* w_d1  = (const float*)d_in[23];
    const float* b_d1  = (const float*)d_in[24];
    const float* gd1   = (const float*)d_in[25];
    const float* bed1  = (const float*)d_in[26];
    const float* w_d2  = (const float*)d_in[27];
    const float* b_d2  = (const float*)d_in[28];
    const float* w_e   = (const float*)d_in[29];
    const float* b_e   = (const float*)d_in[30];
    float* out = (float*)d_out;

    float *qkv, *abar, *seqr, *bufA, *bufB, *d1o, *d1pre, *part;
    cudaGetSymbolAddress((void**)&qkv,   g_qkv);
    cudaGetSymbolAddress((void**)&abar,  g_abar);
    cudaGetSymbolAddress((void**)&seqr,  g_seqr);
    cudaGetSymbolAddress((void**)&bufA,  g_bufA);
    cudaGetSymbolAddress((void**)&bufB,  g_bufB);
    cudaGetSymbolAddress((void**)&d1o,   g_d1o);
    cudaGetSymbolAddress((void**)&d1pre, g_d1pre);
    cudaGetSymbolAddress((void**)&part,  g_part);

    cudaFuncSetAttribute(gemm_bf16x2_k, cudaFuncAttributeMaxDynamicSharedMemorySize, GEMM_SMEM);
    cudaFuncSetAttribute(attn_fused_k,  cudaFuncAttributeMaxDynamicSharedMemorySize, ATTN_SMEM);

    // split-K GEMM helper for the B=256 chain (Kc=128)
    auto gemmsk = [&](const float* A, int lda, const float* W, const float* bias,
                      float* Cfinal, int N, int K) {
        const int Kc = 128;
        int Z = K / Kc;
        dim3 grid(N / 128, BB / 128, Z);
        gemm_bf16x2_k<<<grid, 256, GEMM_SMEM>>>(
            A, lda, 0, Kc, W, K, 0, Kc, nullptr, part, N, (long)BB * N, Kc, Z);
        int total = BB * N;
        reduce_k<<<(total + 255) / 256, 256>>>(part, Z, (long)BB * N, bias, N, Cfinal, total);
    };

    // --- domain GEMM + reduces first (my launches 0-2), then qkv at my idx 3
    //     (R6 evidence: ncu -s 5 captured my idx-3 launch) ---
    {
        const int Kc = 128, Z = 6;                  // K=768
        dim3 grid(384 / 128, BB / 128, Z);
        gemm_bf16x2_k<<<grid, 256, GEMM_SMEM>>>(    // 0
            hs, SS * HH, 0, Kc, w_d1, HH, 0, Kc, nullptr, part, 384, (long)BB * 384, Kc, Z);
        int half = BB * 384 / 2;
        reduce_k<<<(half + 255) / 256, 256>>>(part, Z, (long)BB * 384, b_d1, 384, d1pre, half);               // 1
        reduce_k<<<(half + 255) / 256, 256>>>(part + half, Z, (long)BB * 384, b_d1, 384, d1pre + half, half); // 2
    }

    // --- qkv = hs @ w_qkv.T + b_qkv (M=32768, N=2304, K=768) ---  my launch 3
    gemm_bf16x2_k<<<dim3(2304 / 128, 32768 / 128, 1), 256, GEMM_SMEM>>>(
        hs, HH, 0, 0, w_qkv, HH, 0, 0, b_qkv, qkv, 2304, 0, HH, 1);

    // --- rest of domain path ---
    ln_gelu_k<<<BB, 256>>>(d1pre, gd1, bed1, d1o, 384);
    head5_kernel<<<BB, 160>>>(d1o, 384, w_d2, b_d2, out + 4352);

    // --- fused attention: scores + softmax colmean + GEMV -> abar ---
    attn_fused_k<<<BB * NHH, 256, ATTN_SMEM>>>(qkv, abar);

    // --- seq_repr = abar @ w_out.T + b_out (mean commutes with linear) ---
    gemmsk(abar, HH, w_out, b_out, seqr, HH, HH);

    // --- f1 -> f2 -> ctx -> r1 chain ---
    gemmsk(seqr, HH, w_f1, b_f1, bufA, 1536, HH);
    ln_gelu_k<<<BB, 256>>>(bufA, gf1, bef1, bufB, 1536);

    gemmsk(bufB, 1536, w_f2, b_f2, bufA, 1536, 1536);
    ln_gelu_k<<<BB, 256>>>(bufA, gf2, bef2, bufB, 1536);

    gemmsk(bufB, 1536, w_c, b_c, bufA, HH, 1536);
    ln_gelu_k<<<BB, 256>>>(bufA, gc, bec, bufB, HH);

    gemmsk(bufB, HH, w_r1, b_r1, bufA, 384, HH);
    ln_gelu_k<<<BB, 256>>>(bufA, gr1, ber1, bufB, 384);   // bufB = r1o

    // --- gating softmax + top-2 + expert logits / final logits ---
    gate_kernel<<<BB, 256>>>(bufB, w_r2, b_r2, hs, w_e, b_e, out);

    (void)in_sizes; (void)n_in; (void)out_size;
}

// round 8
// speedup vs baseline: 1.8053x; 1.1438x over previous
#include <cuda_runtime.h>
#include <cuda_bf16.h>
#include <math.h>
#include <stdint.h>

// ---------------- problem constants ----------------
#define BB 256
#define SS 128
#define HH 768
#define NHH 8

// ---------------- scratch (static device globals; no runtime alloc) ----------------
__device__ float g_qkv[75497472];      // 32768 * 2304
__device__ float g_seqr[BB * HH];
__device__ float g_bufA[BB * 1536];
__device__ float g_bufB[BB * 1536];
__device__ float g_d1o[BB * 384];
__device__ float g_d1pre[BB * 384];
__device__ float g_part[4718592];      // split-K partials

// pre-split hi/lo buffers (uint4 for 16B alignment; sizes in uint4 = words/4)
__device__ uint4 g_hs_h[3145728],  g_hs_l[3145728];    // 32768*384 w
__device__ uint4 g_wqkv_h[221184], g_wqkv_l[221184];   // 2304*384 w
__device__ uint4 g_wout_h[73728],  g_wout_l[73728];    // 768*384 w
__device__ uint4 g_wf1_h[147456],  g_wf1_l[147456];    // 1536*384 w
__device__ uint4 g_wf2_h[294912],  g_wf2_l[294912];    // 1536*768 w
__device__ uint4 g_wc_h[147456],   g_wc_l[147456];     // 768*768 w
__device__ uint4 g_wr1_h[36864],   g_wr1_l[36864];     // 384*384 w
__device__ uint4 g_wd1_h[36864],   g_wd1_l[36864];     // 384*384 w
__device__ uint4 g_abar_h[24576],  g_abar_l[24576];    // 256*384 w
__device__ uint4 g_seqr_h[24576],  g_seqr_l[24576];    // 256*384 w
__device__ uint4 g_act1_h[49152],  g_act1_l[49152];    // up to 256*768 w
__device__ uint4 g_act2_h[49152],  g_act2_l[49152];

// ---------------- bf16x2 split: pair (x0,x1) -> hi word + lo word ----------------
__device__ __forceinline__ void split2(float x0, float x1, uint32_t& h, uint32_t& l) {
    asm("cvt.rn.bf16x2.f32 %0, %1, %2;" : "=r"(h) : "f"(x1), "f"(x0));
    __nv_bfloat162 hb = *reinterpret_cast<__nv_bfloat162*>(&h);
    float h0 = __low2float(hb), h1 = __high2float(hb);
    asm("cvt.rn.bf16x2.f32 %0, %1, %2;" : "=r"(l) : "f"(x1 - h1), "f"(x0 - h0));
}

// ---------------- pre-split kernel: float [M,K] (row stride ldaf) -> hi/lo words ----------------
__global__ void presplit_k(const float* __restrict__ in, int ldaf, int Kf,
                           uint32_t* __restrict__ oh, uint32_t* __restrict__ ol, long total4)
{
    long idx = (long)blockIdx.x * blockDim.x + threadIdx.x;   // one per 4 floats
    if (idx < total4) {
        int K4 = Kf >> 2;
        long row = idx / K4;
        int c4 = (int)(idx - row * K4);
        float4 v = *(const float4*)(in + row * ldaf + c4 * 4);
        uint32_t h0, l0, h1, l1;
        split2(v.x, v.y, h0, l0);
        split2(v.z, v.w, h1, l1);
        long w = row * (Kf >> 1) + c4 * 2;
        oh[w] = h0; oh[w + 1] = h1;
        ol[w] = l0; ol[w + 1] = l1;
    }
}

// ---------------- pipelined bf16x2 GEMM ----------------
// Block 128x128, 256 thr (8 warps 2x4), warp 64x32. K-tile 32 (2 x k16 x 3 passes).
// 2-stage cp.async double buffer; ldmatrix.x4 fragment loads.
// smem per stage: AH AL BH BL, each 128 rows x 16 data words, padded stride 20.
#define SMW 20
#define ARR 2560
#define STG 10240
#define GEMM_SMEM (2 * STG * 4)    // 81920 B

#define CPA(dst, src) \
    asm volatile("cp.async.cg.shared.global [%0], [%1], 16;" :: "r"(dst), "l"(src) : "memory")
#define CP_COMMIT() asm volatile("cp.async.commit_group;" ::: "memory")
#define LDSM4(r0, r1, r2, r3, addr) \
    asm volatile("ldmatrix.sync.aligned.m8n8.x4.shared.b16 {%0,%1,%2,%3}, [%4];" \
                 : "=r"(r0), "=r"(r1), "=r"(r2), "=r"(r3) : "r"(addr))
#define MMA_BF16(acc, a0, a1, a2, a3, b0, b1) \
    asm("mma.sync.aligned.m16n8k16.row.col.f32.bf16.bf16.f32 " \
        "{%0,%1,%2,%3},{%4,%5,%6,%7},{%8,%9},{%0,%1,%2,%3};" \
        : "+f"((acc)[0]), "+f"((acc)[1]), "+f"((acc)[2]), "+f"((acc)[3]) \
        : "r"(a0), "r"(a1), "r"(a2), "r"(a3), "r"(b0), "r"(b1))

__global__ void __launch_bounds__(256, 2) gemm_sp_k(
    const uint32_t* __restrict__ Ah, const uint32_t* __restrict__ Al, int ldaw,
    const uint32_t* __restrict__ Wh, const uint32_t* __restrict__ Wl, int ldww,
    int kchunkw,
    const float* __restrict__ bias, float* __restrict__ C, int ldc, long sC,
    int K, int zdiv)
{
    extern __shared__ uint32_t sm[];
    uint32_t smb;
    asm("{ .reg .u64 t; cvta.to.shared.u64 t, %1; cvt.u32.u64 %0, t; }" : "=r"(smb) : "l"(sm));

    int z = blockIdx.z;
    int koffw = (z % zdiv) * kchunkw;
    float* Cb = C + (long)z * sC + (long)blockIdx.y * 128 * ldc + blockIdx.x * 128;

    int tid = threadIdx.x, warp = tid >> 5, lane = tid & 31;
    int wm = warp >> 2, wn = warp & 3, g = lane >> 2, t4 = lane & 3;

    // producer coords: each thread owns row lr, half hf (8 words per array)
    int lr = tid >> 1, hf = tid & 1;
    const uint32_t* pAH = Ah + (long)(blockIdx.y * 128 + lr) * ldaw + koffw + hf * 8;
    const uint32_t* pAL = Al + (long)(blockIdx.y * 128 + lr) * ldaw + koffw + hf * 8;
    const uint32_t* pWH = Wh + (long)(blockIdx.x * 128 + lr) * ldww + koffw + hf * 8;
    const uint32_t* pWL = Wl + (long)(blockIdx.x * 128 + lr) * ldww + koffw + hf * 8;
    uint32_t dstB = smb + (lr * SMW + hf * 8) * 4;

    // consumer lane addresses (ldmatrix): A sel bit0->+8 rows, bit1->+16B; B sel bit0->+16B, bit1->+8 rows
    int laneA = ((lane & 7) + ((lane >> 3) & 1) * 8 + wm * 64) * SMW + ((lane >> 4) & 1) * 4;
    int laneB = ((lane & 7) + ((lane >> 4) & 1) * 8 + wn * 32) * SMW + ((lane >> 3) & 1) * 4;

    float acc[4][4][4];
#pragma unroll
    for (int i = 0; i < 4; i++)
#pragma unroll
        for (int j = 0; j < 4; j++)
#pragma unroll
            for (int e = 0; e < 4; e++) acc[i][j][e] = 0.0f;

    auto prod = [&](int t, int s) {
        uint32_t d = dstB + s * (STG * 4);
        const uint32_t* p = pAH + t * 16;
        CPA(d, p); CPA(d + 16, p + 4);
        p = pAL + t * 16;
        CPA(d + ARR * 4, p); CPA(d + ARR * 4 + 16, p + 4);
        p = pWH + t * 16;
        CPA(d + 2 * ARR * 4, p); CPA(d + 2 * ARR * 4 + 16, p + 4);
        p = pWL + t * 16;
        CPA(d + 3 * ARR * 4, p); CPA(d + 3 * ARR * 4 + 16, p + 4);
        CP_COMMIT();
    };

    int T = K >> 5;
    prod(0, 0);

    for (int t = 0; t < T; t++) {
        int s = t & 1;
        if (t + 1 < T) {
            prod(t + 1, s ^ 1);
            asm volatile("cp.async.wait_group 1;" ::: "memory");
        } else {
            asm volatile("cp.async.wait_group 0;" ::: "memory");
        }
        __syncthreads();

        uint32_t sb = smb + s * (STG * 4);
        uint32_t aH_ = sb + laneA * 4;
        uint32_t aL_ = aH_ + ARR * 4;
        uint32_t bH_ = sb + 2 * ARR * 4 + laneB * 4;
        uint32_t bL_ = bH_ + ARR * 4;
#pragma unroll
        for (int ks = 0; ks < 2; ks++) {
            uint32_t ko = ks * 32;   // 8 words
            uint32_t bh[4][2], bl[4][2];
            LDSM4(bh[0][0], bh[0][1], bh[1][0], bh[1][1], bH_ + ko);
            LDSM4(bh[2][0], bh[2][1], bh[3][0], bh[3][1], bH_ + ko + 16 * SMW * 4);
            LDSM4(bl[0][0], bl[0][1], bl[1][0], bl[1][1], bL_ + ko);
            LDSM4(bl[2][0], bl[2][1], bl[3][0], bl[3][1], bL_ + ko + 16 * SMW * 4);
#pragma unroll
            for (int mt = 0; mt < 4; mt++) {
                uint32_t ah0, ah1, ah2, ah3, al0, al1, al2, al3;
                LDSM4(ah0, ah1, ah2, ah3, aH_ + ko + mt * (16 * SMW * 4));
                LDSM4(al0, al1, al2, al3, aL_ + ko + mt * (16 * SMW * 4));
#pragma unroll
                for (int nt = 0; nt < 4; nt++) {
                    MMA_BF16(acc[mt][nt], ah0, ah1, ah2, ah3, bl[nt][0], bl[nt][1]);
                    MMA_BF16(acc[mt][nt], al0, al1, al2, al3, bh[nt][0], bh[nt][1]);
                    MMA_BF16(acc[mt][nt], ah0, ah1, ah2, ah3, bh[nt][0], bh[nt][1]);
                }
            }
        }
        __syncthreads();
    }

    // epilogue
#pragma unroll
    for (int mt = 0; mt < 4; mt++) {
        int r0 = wm * 64 + mt * 16 + g;
#pragma unroll
        for (int nt = 0; nt < 4; nt++) {
            int c = wn * 32 + nt * 8 + 2 * t4;
            float b0 = 0.f, b1 = 0.f;
            if (bias) { b0 = bias[blockIdx.x * 128 + c]; b1 = bias[blockIdx.x * 128 + c + 1]; }
            float* p0 = Cb + (long)r0 * ldc + c;
            float* p1 = Cb + (long)(r0 + 8) * ldc + c;
            p0[0] = acc[mt][nt][0] + b0; p0[1] = acc[mt][nt][1] + b1;
            p1[0] = acc[mt][nt][2] + b0; p1[1] = acc[mt][nt][3] + b1;
        }
    }
}

// ---------------- attn kernel internals (R7-proven path, self-splitting producer) ----------------
#define AOF_AH 0
#define AOF_AL 2560
#define AOF_BH 5120
#define AOF_BL 7680

__device__ __forceinline__ void attn_load16(const float* __restrict__ src,
                                            uint32_t* __restrict__ sh,
                                            uint32_t* __restrict__ sl, int wbase) {
    uint32_t hw[8], lw[8];
#pragma unroll
    for (int i = 0; i < 4; i++) {
        float4 v = *(const float4*)(src + i * 4);
        split2(v.x, v.y, hw[2 * i], lw[2 * i]);
        split2(v.z, v.w, hw[2 * i + 1], lw[2 * i + 1]);
    }
    *(uint4*)(sh + wbase)     = make_uint4(hw[0], hw[1], hw[2], hw[3]);
    *(uint4*)(sh + wbase + 4) = make_uint4(hw[4], hw[5], hw[6], hw[7]);
    *(uint4*)(sl + wbase)     = make_uint4(lw[0], lw[1], lw[2], lw[3]);
    *(uint4*)(sl + wbase + 4) = make_uint4(lw[4], lw[5], lw[6], lw[7]);
}

__device__ __forceinline__ void attn_mma(float acc[4][4][4], const uint32_t* __restrict__ sm,
                                         int wm, int wn, int g, int t) {
    const uint32_t* AH = sm + AOF_AH;
    const uint32_t* AL = sm + AOF_AL;
    const uint32_t* BH = sm + AOF_BH;
    const uint32_t* BL = sm + AOF_BL;
#pragma unroll
    for (int ks = 0; ks < 2; ks++) {
        int wb = ks * 8 + t;
        uint32_t bh_[4][2], bl_[4][2];
#pragma unroll
        for (int nt = 0; nt < 4; nt++) {
            int n0 = (wn * 32 + nt * 8 + g) * SMW + wb;
            bh_[nt][0] = BH[n0];  bh_[nt][1] = BH[n0 + 4];
            bl_[nt][0] = BL[n0];  bl_[nt][1] = BL[n0 + 4];
        }
#pragma unroll
        for (int mt = 0; mt < 4; mt++) {
            int r0 = (wm * 64 + mt * 16 + g) * SMW + wb;
            int r1 = r0 + 8 * SMW;
            uint32_t ah0 = AH[r0], ah1 = AH[r1], ah2 = AH[r0 + 4], ah3 = AH[r1 + 4];
            uint32_t al0 = AL[r0], al1 = AL[r1], al2 = AL[r0 + 4], al3 = AL[r1 + 4];
#pragma unroll
            for (int nt = 0; nt < 4; nt++) {
                MMA_BF16(acc[mt][nt], ah0, ah1, ah2, ah3, bl_[nt][0], bl_[nt][1]);
                MMA_BF16(acc[mt][nt], al0, al1, al2, al3, bh_[nt][0], bh_[nt][1]);
                MMA_BF16(acc[mt][nt], ah0, ah1, ah2, ah3, bh_[nt][0], bh_[nt][1]);
            }
        }
    }
}

// fused attention per head: scores + softmax colmean + GEMV -> abar (pre-split output)
#define ATTN_SMEM ((128 * 132 + 8 * 128) * 4)
__global__ void __launch_bounds__(256, 2) attn_fused_k(
    const float* __restrict__ qkv, uint32_t* __restrict__ abh, uint32_t* __restrict__ abl)
{
    extern __shared__ uint32_t sm[];
    int bhid = blockIdx.x;
    int b = bhid >> 3, h = bhid & 7;
    const float* base = qkv + (long)b * SS * 2304 + h * 96;

    int tid = threadIdx.x, warp = tid >> 5, lane = tid & 31;
    int wm = warp >> 2, wn = warp & 3, g = lane >> 2, t = lane & 3;

    int lr = tid >> 1, hf = (tid & 1);
    int wbase = lr * SMW + hf * 8;
    const float* arow = base + (long)lr * 2304 + hf * 16;
    const float* wrow = base + 768 + (long)lr * 2304 + hf * 16;

    float acc[4][4][4];
#pragma unroll
    for (int i = 0; i < 4; i++)
#pragma unroll
        for (int j = 0; j < 4; j++)
#pragma unroll
            for (int e = 0; e < 4; e++) acc[i][j][e] = 0.0f;

#pragma unroll
    for (int k0 = 0; k0 < 96; k0 += 32) {
        attn_load16(arow + k0, sm + AOF_AH, sm + AOF_AL, wbase);
        attn_load16(wrow + k0, sm + AOF_BH, sm + AOF_BL, wbase);
        __syncthreads();
        attn_mma(acc, sm, wm, wn, g, t);
        __syncthreads();
    }

    const float scale = 0.10206207261596577f;   // 1/sqrt(96)
    float* sc = (float*)sm;
    float* wa = (float*)(sm + 128 * 132);
#pragma unroll
    for (int mt = 0; mt < 4; mt++) {
        int r0 = wm * 64 + mt * 16 + g;
#pragma unroll
        for (int nt = 0; nt < 4; nt++) {
            int c = wn * 32 + nt * 8 + 2 * t;
            sc[r0 * 132 + c]           = acc[mt][nt][0] * scale;
            sc[r0 * 132 + c + 1]       = acc[mt][nt][1] * scale;
            sc[(r0 + 8) * 132 + c]     = acc[mt][nt][2] * scale;
            sc[(r0 + 8) * 132 + c + 1] = acc[mt][nt][3] * scale;
        }
    }
    __syncthreads();

#pragma unroll
    for (int j = 0; j < 4; j++) wa[warp * 128 + lane + 32 * j] = 0.0f;
    __syncwarp();

    for (int s = warp; s < 128; s += 8) {
        float x0 = sc[s * 132 + lane];
        float x1 = sc[s * 132 + lane + 32];
        float x2 = sc[s * 132 + lane + 64];
        float x3 = sc[s * 132 + lane + 96];
        float m = fmaxf(fmaxf(x0, x1), fmaxf(x2, x3));
#pragma unroll
        for (int o = 16; o; o >>= 1) m = fmaxf(m, __shfl_xor_sync(0xffffffffu, m, o));
        float e0 = expf(x0 - m), e1 = expf(x1 - m), e2 = expf(x2 - m), e3 = expf(x3 - m);
        float smm = e0 + e1 + e2 + e3;
#pragma unroll
        for (int o = 16; o; o >>= 1) smm += __shfl_xor_sync(0xffffffffu, smm, o);
        float inv = 1.0f / smm;
        wa[warp * 128 + lane]      += e0 * inv;
        wa[warp * 128 + lane + 32] += e1 * inv;
        wa[warp * 128 + lane + 64] += e2 * inv;
        wa[warp * 128 + lane + 96] += e3 * inv;
    }
    __syncthreads();
    if (warp == 0) {
#pragma unroll
        for (int j = 0; j < 4; j++) {
            int c = lane + 32 * j;
            float s = 0.f;
#pragma unroll
            for (int w = 0; w < 8; w++) s += wa[w * 128 + c];
            wa[c] = s;
        }
    }
    __syncthreads();

    float a = 0.0f;
    if (tid < 96) {
        const float* v = qkv + (long)b * SS * 2304 + 1536 + h * 96 + tid;
#pragma unroll 8
        for (int k = 0; k < 128; k++) a = fmaf(wa[k], v[(long)k * 2304], a);
        a *= (1.0f / 128.0f);
    }
    __syncthreads();
    if (tid < 96) sc[tid] = a;     // stage (sc region free now)
    __syncthreads();
    if (tid < 48) {
        uint32_t hw, lw;
        split2(sc[2 * tid], sc[2 * tid + 1], hw, lw);
        long w = (long)b * 384 + h * 48 + tid;
        abh[w] = hw;
        abl[w] = lw;
    }
}

// ---------------- split-K reduction (pairwise; optional split output) ----------------
__global__ void reduce_k(const float* __restrict__ part, int Z, long stride,
                         const float* __restrict__ bias, int N,
                         float* __restrict__ C, uint32_t* __restrict__ Ch,
                         uint32_t* __restrict__ Cl, int totalPairs)
{
    int p = blockIdx.x * blockDim.x + threadIdx.x;
    if (p < totalPairs) {
        int i0 = 2 * p;
        float s0 = 0.f, s1 = 0.f;
        for (int zz = 0; zz < Z; zz++) {
            s0 += part[(long)zz * stride + i0];
            s1 += part[(long)zz * stride + i0 + 1];
        }
        s0 += bias[i0 % N];
        s1 += bias[(i0 + 1) % N];
        C[i0] = s0; C[i0 + 1] = s1;
        if (Ch) {
            uint32_t hw, lw;
            split2(s0, s1, hw, lw);
            Ch[p] = hw; Cl[p] = lw;
        }
    }
}

// ---------------- fused LayerNorm + exact GELU (optional split output) ----------------
__global__ void ln_gelu_k(const float* __restrict__ in, const float* __restrict__ gm,
                          const float* __restrict__ be, float* __restrict__ out,
                          uint32_t* __restrict__ oh, uint32_t* __restrict__ ol, int N)
{
    int row = blockIdx.x;
    const float* x = in + (long)row * N;
    float* y = out + (long)row * N;
    int tid = threadIdx.x, warp = tid >> 5, lane = tid & 31;

    float s = 0.f, s2 = 0.f;
    for (int i = tid; i < N; i += blockDim.x) { float v = x[i]; s += v; s2 += v * v; }
#pragma unroll
    for (int o = 16; o; o >>= 1) { s += __shfl_xor_sync(0xffffffffu, s, o); s2 += __shfl_xor_sync(0xffffffffu, s2, o); }
    __shared__ float rs[8], rs2[8], sm_mean, sm_rstd;
    if (lane == 0) { rs[warp] = s; rs2[warp] = s2; }
    __syncthreads();
    if (tid == 0) {
        float S = 0.f, S2 = 0.f;
        for (int w = 0; w < 8; w++) { S += rs[w]; S2 += rs2[w]; }
        float mean = S / N;
        float var = S2 / N - mean * mean;
        sm_mean = mean;
        sm_rstd = rsqrtf(var + 1e-5f);
    }
    __syncthreads();
    float mean = sm_mean, rstd = sm_rstd;
    int half = N >> 1;
    for (int p = tid; p < half; p += blockDim.x) {
        float v0 = (x[2 * p] - mean) * rstd * gm[2 * p] + be[2 * p];
        float v1 = (x[2 * p + 1] - mean) * rstd * gm[2 * p + 1] + be[2 * p + 1];
        v0 = 0.5f * v0 * (1.0f + erff(v0 * 0.70710678118654752f));
        v1 = 0.5f * v1 * (1.0f + erff(v1 * 0.70710678118654752f));
        y[2 * p] = v0; y[2 * p + 1] = v1;
        if (oh) {
            uint32_t hw, lw;
            split2(v0, v1, hw, lw);
            oh[(long)row * half + p] = hw;
            ol[(long)row * half + p] = lw;
        }
    }
}

// ---------------- warp dot helper ----------------
__device__ __forceinline__ float warp_dot(const float* a, const float* b, int n, int lane)
{
    float s = 0.f;
    for (int i = lane; i < n; i += 32) s = fmaf(a[i], b[i], s);
#pragma unroll
    for (int o = 16; o; o >>= 1) s += __shfl_xor_sync(0xffffffffu, s, o);
    return s;
}

// ---------------- small 5-way head (domain logits) ----------------
__global__ void head5_kernel(const float* __restrict__ in, int Kin,
                             const float* __restrict__ w, const float* __restrict__ bias,
                             float* __restrict__ out)
{
    int b = blockIdx.x, warp = threadIdx.x >> 5, lane = threadIdx.x & 31;
    if (warp < 5) {
        float s = warp_dot(in + (long)b * Kin, w + (long)warp * Kin, Kin, lane);
        if (lane == 0) out[b * 5 + warp] = s + bias[warp];
    }
}

// ---------------- gating softmax + top-2 + expert mix ----------------
__global__ void gate_kernel(const float* __restrict__ r1o,
                            const float* __restrict__ w_r2, const float* __restrict__ b_r2,
                            const float* __restrict__ hs,
                            const float* __restrict__ w_e, const float* __restrict__ b_e,
                            float* __restrict__ out)
{
    __shared__ float gl[5], ae[10];
    int b = blockIdx.x, tid = threadIdx.x, warp = tid >> 5, lane = tid & 31;

    if (warp < 5) {
        float s = warp_dot(r1o + (long)b * 384, w_r2 + (long)warp * 384, 384, lane);
        if (lane == 0) gl[warp] = s + b_r2[warp];
    }
    const float* cls = hs + (long)b * SS * HH;
    for (int idx = warp; idx < 10; idx += 8) {
        float s = warp_dot(cls, w_e + (long)idx * HH, HH, lane);
        if (lane == 0) ae[idx] = s + b_e[idx];
    }
    __syncthreads();

    if (tid == 0) {
        float m = gl[0];
        for (int j = 1; j < 5; j++) m = fmaxf(m, gl[j]);
        float e[5], sum = 0.f;
        for (int j = 0; j < 5; j++) { e[j] = expf(gl[j] - m); sum += e[j]; }
        float p[5];
        for (int j = 0; j < 5; j++) { p[j] = e[j] / sum; out[512 + b * 5 + j] = p[j]; }
        int i1 = 0;
        for (int j = 1; j < 5; j++) if (p[j] > p[i1]) i1 = j;
        int i2 = -1;
        for (int j = 0; j < 5; j++) if (j != i1 && (i2 < 0 || p[j] > p[i2])) i2 = j;
        float ps = p[i1] + p[i2];
        float w1 = p[i1] / ps, w2 = p[i2] / ps;
        for (int ee = 0; ee < 5; ee++) {
            bool sel = (ee == i1) || (ee == i2);
            out[1792 + b * 10 + ee * 2 + 0] = sel ? ae[ee * 2 + 0] : 0.0f;
            out[1792 + b * 10 + ee * 2 + 1] = sel ? ae[ee * 2 + 1] : 0.0f;
        }
        out[b * 2 + 0] = w1 * ae[i1 * 2 + 0] + w2 * ae[i2 * 2 + 0];
        out[b * 2 + 1] = w1 * ae[i1 * 2 + 1] + w2 * ae[i2 * 2 + 1];
    }
}

// ---------------- host launcher ----------------
extern "C" void kernel_launch(void* const* d_in, const int* in_sizes, int n_in,
                              void* d_out, int out_size)
{
    const float* hs    = (const float*)d_in[0];
    const float* w_qkv = (const float*)d_in[1];
    const float* b_qkv = (const float*)d_in[2];
    const float* w_out = (const float*)d_in[3];
    const float* b_out = (const float*)d_in[4];
    const float* w_f1  = (const float*)d_in[5];
    const float* b_f1  = (const float*)d_in[6];
    const float* gf1   = (const float*)d_in[7];
    const float* bef1  = (const float*)d_in[8];
    const float* w_f2  = (const float*)d_in[9];
    const float* b_f2  = (const float*)d_in[10];
    const float* gf2   = (const float*)d_in[11];
    const float* bef2  = (const float*)d_in[12];
    const float* w_c   = (const float*)d_in[13];
    const float* b_c   = (const float*)d_in[14];
    const float* gc    = (const float*)d_in[15];
    const float* bec   = (const float*)d_in[16];
    const float* w_r1  = (const float*)d_in[17];
    const float* b_r1  = (const float*)d_in[18];
    const float* gr1   = (const float*)d_in[19];
    const float* ber1  = (const float*)d_in[20];
    const float* w_r2  = (const float*)d_in[21];
    const float* b_r2  = (const float*)d_in[22];
    const float* w_d1  = (const float*)d_in[23];
    const float* b_d1  = (const float*)d_in[24];
    const float* gd1   = (const float*)d_in[25];
    const float* bed1  = (const float*)d_in[26];
    const float* w_d2  = (const float*)d_in[27];
    const float* b_d2  = (const float*)d_in[28];
    const float* w_e   = (const float*)d_in[29];
    const float* b_e   = (const float*)d_in[30];
    float* out = (float*)d_out;

    float *qkv, *seqr, *bufA, *bufB, *d1o, *d1pre, *part;
    cudaGetSymbolAddress((void**)&qkv,   g_qkv);
    cudaGetSymbolAddress((void**)&seqr,  g_seqr);
    cudaGetSymbolAddress((void**)&bufA,  g_bufA);
    cudaGetSymbolAddress((void**)&bufB,  g_bufB);
    cudaGetSymbolAddress((void**)&d1o,   g_d1o);
    cudaGetSymbolAddress((void**)&d1pre, g_d1pre);
    cudaGetSymbolAddress((void**)&part,  g_part);

    uint32_t *hsh, *hsl, *qkh, *qkl, *outh, *outl, *f1h, *f1l, *f2h, *f2l;
    uint32_t *ch, *cl, *r1h, *r1l, *d1h, *d1l, *abh, *abl, *sqh, *sql;
    uint32_t *a1h, *a1l, *a2h, *a2l;
    cudaGetSymbolAddress((void**)&hsh, g_hs_h);   cudaGetSymbolAddress((void**)&hsl, g_hs_l);
    cudaGetSymbolAddress((void**)&qkh, g_wqkv_h); cudaGetSymbolAddress((void**)&qkl, g_wqkv_l);
    cudaGetSymbolAddress((void**)&outh, g_wout_h); cudaGetSymbolAddress((void**)&outl, g_wout_l);
    cudaGetSymbolAddress((void**)&f1h, g_wf1_h);  cudaGetSymbolAddress((void**)&f1l, g_wf1_l);
    cudaGetSymbolAddress((void**)&f2h, g_wf2_h);  cudaGetSymbolAddress((void**)&f2l, g_wf2_l);
    cudaGetSymbolAddress((void**)&ch,  g_wc_h);   cudaGetSymbolAddress((void**)&cl,  g_wc_l);
    cudaGetSymbolAddress((void**)&r1h, g_wr1_h);  cudaGetSymbolAddress((void**)&r1l, g_wr1_l);
    cudaGetSymbolAddress((void**)&d1h, g_wd1_h);  cudaGetSymbolAddress((void**)&d1l, g_wd1_l);
    cudaGetSymbolAddress((void**)&abh, g_abar_h); cudaGetSymbolAddress((void**)&abl, g_abar_l);
    cudaGetSymbolAddress((void**)&sqh, g_seqr_h); cudaGetSymbolAddress((void**)&sql, g_seqr_l);
    cudaGetSymbolAddress((void**)&a1h, g_act1_h); cudaGetSymbolAddress((void**)&a1l, g_act1_l);
    cudaGetSymbolAddress((void**)&a2h, g_act2_h); cudaGetSymbolAddress((void**)&a2l, g_act2_l);

    cudaFuncSetAttribute(gemm_sp_k,    cudaFuncAttributeMaxDynamicSharedMemorySize, GEMM_SMEM);
    cudaFuncSetAttribute(attn_fused_k, cudaFuncAttributeMaxDynamicSharedMemorySize, ATTN_SMEM);

    auto split = [&](const float* in, int lda, int M, int K, uint32_t* oh, uint32_t* ol) {
        long t4 = (long)M * K / 4;
        presplit_k<<<(unsigned)((t4 + 255) / 256), 256>>>(in, lda, K, oh, ol, t4);
    };

    // 0-2: pre-split hs / w_qkv / w_d1  (qkv at launch idx 3 for ncu -s 5 capture)
    split(hs,    768, 32768, 768, hsh, hsl);          // 0
    split(w_qkv, 768, 2304,  768, qkh, qkl);          // 1
    split(w_d1,  768, 384,   768, d1h, d1l);          // 2

    // 3: qkv = hs @ w_qkv.T + b_qkv
    gemm_sp_k<<<dim3(18, 256, 1), 256, GEMM_SMEM>>>(
        hsh, hsl, 384, qkh, qkl, 384, 0, b_qkv, qkv, 2304, 0, 768, 1);

    // remaining weight pre-splits
    split(w_out, 768,  768,  768,  outh, outl);
    split(w_f1,  768,  1536, 768,  f1h,  f1l);
    split(w_f2,  1536, 1536, 1536, f2h,  f2l);
    split(w_c,   1536, 768,  1536, ch,   cl);
    split(w_r1,  768,  384,  768,  r1h,  r1l);

    // split-K GEMM helper (Kc = 128 -> kchunkw = 64)
    auto gemmsk = [&](const uint32_t* Ah, const uint32_t* Al, int ldaw,
                      const uint32_t* Wh, const uint32_t* Wl, int ldww,
                      const float* bias, float* Cf, uint32_t* Cfh, uint32_t* Cfl,
                      int N, int K) {
        int Z = K / 128;
        dim3 grid(N / 128, BB / 128, Z);
        gemm_sp_k<<<grid, 256, GEMM_SMEM>>>(
            Ah, Al, ldaw, Wh, Wl, ldww, 64, nullptr, part, N, (long)BB * N, 128, Z);
        int pairs = BB * N / 2;
        reduce_k<<<(pairs + 255) / 256, 256>>>(part, Z, (long)BB * N, bias, N,
                                               Cf, Cfh, Cfl, pairs);
    };

    // domain path: d1pre = cls(hs) @ w_d1.T + b_d1 ; ln+gelu ; head5
    gemmsk(hsh, hsl, SS * 384, d1h, d1l, 384, b_d1, d1pre, nullptr, nullptr, 384, 768);
    ln_gelu_k<<<BB, 256>>>(d1pre, gd1, bed1, d1o, nullptr, nullptr, 384);
    head5_kernel<<<BB, 160>>>(d1o, 384, w_d2, b_d2, out + 4352);

    // fused attention -> abar (split)
    attn_fused_k<<<BB * NHH, 256, ATTN_SMEM>>>(qkv, abh, abl);

    // seq_repr = abar @ w_out.T + b_out
    gemmsk(abh, abl, 384, outh, outl, 384, b_out, seqr, sqh, sql, 768, 768);

    // f1 -> f2 -> ctx -> r1 chain
    gemmsk(sqh, sql, 384, f1h, f1l, 384, b_f1, bufA, nullptr, nullptr, 1536, 768);
    ln_gelu_k<<<BB, 256>>>(bufA, gf1, bef1, bufB, a1h, a1l, 1536);

    gemmsk(a1h, a1l, 768, f2h, f2l, 768, b_f2, bufA, nullptr, nullptr, 1536, 1536);
    ln_gelu_k<<<BB, 256>>>(bufA, gf2, bef2, bufB, a2h, a2l, 1536);

    gemmsk(a2h, a2l, 768, ch, cl, 768, b_c, bufA, nullptr, nullptr, 768, 1536);
    ln_gelu_k<<<BB, 256>>>(bufA, gc, bec, bufB, a1h, a1l, 768);

    gemmsk(a1h, a1l, 384, r1h, r1l, 384, b_r1, bufA, nullptr, nullptr, 384, 768);
    ln_gelu_k<<<BB, 256>>>(bufA, gr1, ber1, bufB, nullptr, nullptr, 384);   // bufB = r1o

    // gating softmax + top-2 + expert logits / final logits
    gate_kernel<<<BB, 256>>>(bufB, w_r2, b_r2, hs, w_e, b_e, out);

    (void)in_sizes; (void)n_in; (void)out_size;
}

// round 9
// speedup vs baseline: 1.8387x; 1.0185x over previous
#include <cuda_runtime.h>
#include <cuda_bf16.h>
#include <math.h>
#include <stdint.h>

// ---------------- problem constants ----------------
#define BB 256
#define SS 128
#define HH 768
#define NHH 8

// ---------------- scratch (static device globals; no runtime alloc) ----------------
__device__ float g_qkv[75497472];      // 32768 * 2304
__device__ float g_seqr[BB * HH];
__device__ float g_bufA[BB * 1536];
__device__ float g_bufB[BB * 1536];
__device__ float g_d1o[BB * 384];
__device__ float g_part[4718592];      // split-K partials

// pre-split hi/lo buffers (uint4 for 16B alignment)
__device__ uint4 g_hs_h[3145728],  g_hs_l[3145728];    // 32768*384 w
__device__ uint4 g_wqkv_h[221184], g_wqkv_l[221184];   // 2304*384 w
__device__ uint4 g_wout_h[73728],  g_wout_l[73728];    // 768*384 w
__device__ uint4 g_wf1_h[147456],  g_wf1_l[147456];    // 1536*384 w
__device__ uint4 g_wf2_h[294912],  g_wf2_l[294912];    // 1536*768 w
__device__ uint4 g_wc_h[147456],   g_wc_l[147456];     // 768*768 w
__device__ uint4 g_wr1_h[36864],   g_wr1_l[36864];     // 384*384 w
__device__ uint4 g_wd1_h[36864],   g_wd1_l[36864];     // 384*384 w
__device__ uint4 g_abar_h[24576],  g_abar_l[24576];    // 256*384 w
__device__ uint4 g_seqr_h[24576],  g_seqr_l[24576];    // 256*384 w
__device__ uint4 g_act1_h[49152],  g_act1_l[49152];    // up to 256*768 w
__device__ uint4 g_act2_h[49152],  g_act2_l[49152];

// ---------------- bf16x2 split: pair (x0,x1) -> hi word + lo word ----------------
__device__ __forceinline__ void split2(float x0, float x1, uint32_t& h, uint32_t& l) {
    asm("cvt.rn.bf16x2.f32 %0, %1, %2;" : "=r"(h) : "f"(x1), "f"(x0));
    __nv_bfloat162 hb = *reinterpret_cast<__nv_bfloat162*>(&h);
    float h0 = __low2float(hb), h1 = __high2float(hb);
    asm("cvt.rn.bf16x2.f32 %0, %1, %2;" : "=r"(l) : "f"(x1 - h1), "f"(x0 - h0));
}

// ---------------- pre-split kernel ----------------
__global__ void presplit_k(const float* __restrict__ in, int ldaf, int Kf,
                           uint32_t* __restrict__ oh, uint32_t* __restrict__ ol, long total4)
{
    long idx = (long)blockIdx.x * blockDim.x + threadIdx.x;
    if (idx < total4) {
        int K4 = Kf >> 2;
        long row = idx / K4;
        int c4 = (int)(idx - row * K4);
        float4 v = *(const float4*)(in + row * ldaf + c4 * 4);
        uint32_t h0, l0, h1, l1;
        split2(v.x, v.y, h0, l0);
        split2(v.z, v.w, h1, l1);
        long w = row * (Kf >> 1) + c4 * 2;
        oh[w] = h0; oh[w + 1] = h1;
        ol[w] = l0; ol[w + 1] = l1;
    }
}

// ---------------- pipelined bf16x2 GEMM (4-stage, K-tile 16, 1 sync/iter) ----------------
// Block 128x128, 256 thr (8 warps 2x4), warp 64x32.
// smem per stage: AH AL BH BL, each 128 rows x 8 data words, padded stride 12.
#define SMW 12
#define ARR 1536                     // words per array
#define STG 6144                     // words per stage (4 arrays)
#define GEMM_SMEM (4 * STG * 4)      // 98304 B

#define CPA(dst, src) \
    asm volatile("cp.async.cg.shared.global [%0], [%1], 16;" :: "r"(dst), "l"(src) : "memory")
#define CP_COMMIT() asm volatile("cp.async.commit_group;" ::: "memory")
#define LDSM4(r0, r1, r2, r3, addr) \
    asm volatile("ldmatrix.sync.aligned.m8n8.x4.shared.b16 {%0,%1,%2,%3}, [%4];" \
                 : "=r"(r0), "=r"(r1), "=r"(r2), "=r"(r3) : "r"(addr))
#define MMA_BF16(acc, a0, a1, a2, a3, b0, b1) \
    asm("mma.sync.aligned.m16n8k16.row.col.f32.bf16.bf16.f32 " \
        "{%0,%1,%2,%3},{%4,%5,%6,%7},{%8,%9},{%0,%1,%2,%3};" \
        : "+f"((acc)[0]), "+f"((acc)[1]), "+f"((acc)[2]), "+f"((acc)[3]) \
        : "r"(a0), "r"(a1), "r"(a2), "r"(a3), "r"(b0), "r"(b1))

__global__ void __launch_bounds__(256, 2) gemm_sp_k(
    const uint32_t* __restrict__ Ah, const uint32_t* __restrict__ Al, int ldaw,
    const uint32_t* __restrict__ Wh, const uint32_t* __restrict__ Wl, int ldww,
    int kchunkw,
    const float* __restrict__ bias, float* __restrict__ C, int ldc, long sC,
    int K, int zdiv)
{
    extern __shared__ uint32_t sm[];
    uint32_t smb;
    asm("{ .reg .u64 t; cvta.to.shared.u64 t, %1; cvt.u32.u64 %0, t; }" : "=r"(smb) : "l"(sm));

    int z = blockIdx.z;
    int koffw = (z % zdiv) * kchunkw;
    float* Cb = C + (long)z * sC + (long)blockIdx.y * 128 * ldc + blockIdx.x * 128;

    int tid = threadIdx.x, warp = tid >> 5, lane = tid & 31;
    int wm = warp >> 2, wn = warp & 3, g = lane >> 2, t4 = lane & 3;

    // producer: thread owns row lr, half hf (4 words per array per k16 tile)
    int lr = tid >> 1, hf = tid & 1;
    const uint32_t* pAH = Ah + (long)(blockIdx.y * 128 + lr) * ldaw + koffw + hf * 4;
    const uint32_t* pAL = Al + (long)(blockIdx.y * 128 + lr) * ldaw + koffw + hf * 4;
    const uint32_t* pWH = Wh + (long)(blockIdx.x * 128 + lr) * ldww + koffw + hf * 4;
    const uint32_t* pWL = Wl + (long)(blockIdx.x * 128 + lr) * ldww + koffw + hf * 4;
    uint32_t dstB = smb + (lr * SMW + hf * 4) * 4;

    // consumer lane addresses (ldmatrix, proven mapping from R8)
    int laneA = ((lane & 7) + ((lane >> 3) & 1) * 8 + wm * 64) * SMW + ((lane >> 4) & 1) * 4;
    int laneB = ((lane & 7) + ((lane >> 4) & 1) * 8 + wn * 32) * SMW + ((lane >> 3) & 1) * 4;

    float acc[4][4][4];
#pragma unroll
    for (int i = 0; i < 4; i++)
#pragma unroll
        for (int j = 0; j < 4; j++)
#pragma unroll
            for (int e = 0; e < 4; e++) acc[i][j][e] = 0.0f;

    auto prod = [&](int t, int s) {
        uint32_t d = dstB + s * (STG * 4);
        CPA(d,               pAH + t * 8);
        CPA(d + ARR * 4,     pAL + t * 8);
        CPA(d + 2 * ARR * 4, pWH + t * 8);
        CPA(d + 3 * ARR * 4, pWL + t * 8);
    };

    int T = K >> 4;           // k16 tiles (K >= 128 always -> T >= 8)
    prod(0, 0); CP_COMMIT();
    prod(1, 1); CP_COMMIT();
    prod(2, 2); CP_COMMIT();

    for (int t = 0; t < T; t++) {
        asm volatile("cp.async.wait_group 2;" ::: "memory");
        __syncthreads();
        if (t + 3 < T) prod(t + 3, (t + 3) & 3);
        CP_COMMIT();          // empty group at tail keeps wait count constant

        uint32_t sb = smb + (t & 3) * (STG * 4);
        uint32_t aH_ = sb + laneA * 4;
        uint32_t aL_ = aH_ + ARR * 4;
        uint32_t bH_ = sb + 2 * ARR * 4 + laneB * 4;
        uint32_t bL_ = bH_ + ARR * 4;

        uint32_t bh[4][2], bl[4][2];
        LDSM4(bh[0][0], bh[0][1], bh[1][0], bh[1][1], bH_);
        LDSM4(bh[2][0], bh[2][1], bh[3][0], bh[3][1], bH_ + 16 * SMW * 4);
        LDSM4(bl[0][0], bl[0][1], bl[1][0], bl[1][1], bL_);
        LDSM4(bl[2][0], bl[2][1], bl[3][0], bl[3][1], bL_ + 16 * SMW * 4);
#pragma unroll
        for (int mt = 0; mt < 4; mt++) {
            uint32_t ah0, ah1, ah2, ah3, al0, al1, al2, al3;
            LDSM4(ah0, ah1, ah2, ah3, aH_ + mt * (16 * SMW * 4));
            LDSM4(al0, al1, al2, al3, aL_ + mt * (16 * SMW * 4));
#pragma unroll
            for (int nt = 0; nt < 4; nt++) {
                MMA_BF16(acc[mt][nt], ah0, ah1, ah2, ah3, bl[nt][0], bl[nt][1]);
                MMA_BF16(acc[mt][nt], al0, al1, al2, al3, bh[nt][0], bh[nt][1]);
                MMA_BF16(acc[mt][nt], ah0, ah1, ah2, ah3, bh[nt][0], bh[nt][1]);
            }
        }
    }

    __syncthreads();
    // epilogue
#pragma unroll
    for (int mt = 0; mt < 4; mt++) {
        int r0 = wm * 64 + mt * 16 + g;
#pragma unroll
        for (int nt = 0; nt < 4; nt++) {
            int c = wn * 32 + nt * 8 + 2 * t4;
            float b0 = 0.f, b1 = 0.f;
            if (bias) { b0 = bias[blockIdx.x * 128 + c]; b1 = bias[blockIdx.x * 128 + c + 1]; }
            float* p0 = Cb + (long)r0 * ldc + c;
            float* p1 = Cb + (long)(r0 + 8) * ldc + c;
            p0[0] = acc[mt][nt][0] + b0; p0[1] = acc[mt][nt][1] + b1;
            p1[0] = acc[mt][nt][2] + b0; p1[1] = acc[mt][nt][3] + b1;
        }
    }
}

// ---------------- attn kernel (R7/R8-proven path) ----------------
#define ASMW 20
#define AOF_AH 0
#define AOF_AL 2560
#define AOF_BH 5120
#define AOF_BL 7680
#define ATTN_SMEM ((128 * 132 + 8 * 128) * 4)

__device__ __forceinline__ void attn_load16(const float* __restrict__ src,
                                            uint32_t* __restrict__ sh,
                                            uint32_t* __restrict__ sl, int wbase) {
    uint32_t hw[8], lw[8];
#pragma unroll
    for (int i = 0; i < 4; i++) {
        float4 v = *(const float4*)(src + i * 4);
        split2(v.x, v.y, hw[2 * i], lw[2 * i]);
        split2(v.z, v.w, hw[2 * i + 1], lw[2 * i + 1]);
    }
    *(uint4*)(sh + wbase)     = make_uint4(hw[0], hw[1], hw[2], hw[3]);
    *(uint4*)(sh + wbase + 4) = make_uint4(hw[4], hw[5], hw[6], hw[7]);
    *(uint4*)(sl + wbase)     = make_uint4(lw[0], lw[1], lw[2], lw[3]);
    *(uint4*)(sl + wbase + 4) = make_uint4(lw[4], lw[5], lw[6], lw[7]);
}

__device__ __forceinline__ void attn_mma(float acc[4][4][4], const uint32_t* __restrict__ sm,
                                         int wm, int wn, int g, int t) {
    const uint32_t* AH = sm + AOF_AH;
    const uint32_t* AL = sm + AOF_AL;
    const uint32_t* BH = sm + AOF_BH;
    const uint32_t* BL = sm + AOF_BL;
#pragma unroll
    for (int ks = 0; ks < 2; ks++) {
        int wb = ks * 8 + t;
        uint32_t bh_[4][2], bl_[4][2];
#pragma unroll
        for (int nt = 0; nt < 4; nt++) {
            int n0 = (wn * 32 + nt * 8 + g) * ASMW + wb;
            bh_[nt][0] = BH[n0];  bh_[nt][1] = BH[n0 + 4];
            bl_[nt][0] = BL[n0];  bl_[nt][1] = BL[n0 + 4];
        }
#pragma unroll
        for (int mt = 0; mt < 4; mt++) {
            int r0 = (wm * 64 + mt * 16 + g) * ASMW + wb;
            int r1 = r0 + 8 * ASMW;
            uint32_t ah0 = AH[r0], ah1 = AH[r1], ah2 = AH[r0 + 4], ah3 = AH[r1 + 4];
            uint32_t al0 = AL[r0], al1 = AL[r1], al2 = AL[r0 + 4], al3 = AL[r1 + 4];
#pragma unroll
            for (int nt = 0; nt < 4; nt++) {
                MMA_BF16(acc[mt][nt], ah0, ah1, ah2, ah3, bl_[nt][0], bl_[nt][1]);
                MMA_BF16(acc[mt][nt], al0, al1, al2, al3, bh_[nt][0], bh_[nt][1]);
                MMA_BF16(acc[mt][nt], ah0, ah1, ah2, ah3, bh_[nt][0], bh_[nt][1]);
            }
        }
    }
}

__global__ void __launch_bounds__(256, 2) attn_fused_k(
    const float* __restrict__ qkv, uint32_t* __restrict__ abh, uint32_t* __restrict__ abl)
{
    extern __shared__ uint32_t sm[];
    int bhid = blockIdx.x;
    int b = bhid >> 3, h = bhid & 7;
    const float* base = qkv + (long)b * SS * 2304 + h * 96;

    int tid = threadIdx.x, warp = tid >> 5, lane = tid & 31;
    int wm = warp >> 2, wn = warp & 3, g = lane >> 2, t = lane & 3;

    int lr = tid >> 1, hf = (tid & 1);
    int wbase = lr * ASMW + hf * 8;
    const float* arow = base + (long)lr * 2304 + hf * 16;
    const float* wrow = base + 768 + (long)lr * 2304 + hf * 16;

    float acc[4][4][4];
#pragma unroll
    for (int i = 0; i < 4; i++)
#pragma unroll
        for (int j = 0; j < 4; j++)
#pragma unroll
            for (int e = 0; e < 4; e++) acc[i][j][e] = 0.0f;

#pragma unroll
    for (int k0 = 0; k0 < 96; k0 += 32) {
        attn_load16(arow + k0, sm + AOF_AH, sm + AOF_AL, wbase);
        attn_load16(wrow + k0, sm + AOF_BH, sm + AOF_BL, wbase);
        __syncthreads();
        attn_mma(acc, sm, wm, wn, g, t);
        __syncthreads();
    }

    const float scale = 0.10206207261596577f;   // 1/sqrt(96)
    float* sc = (float*)sm;
    float* wa = (float*)(sm + 128 * 132);
#pragma unroll
    for (int mt = 0; mt < 4; mt++) {
        int r0 = wm * 64 + mt * 16 + g;
#pragma unroll
        for (int nt = 0; nt < 4; nt++) {
            int c = wn * 32 + nt * 8 + 2 * t;
            sc[r0 * 132 + c]           = acc[mt][nt][0] * scale;
            sc[r0 * 132 + c + 1]       = acc[mt][nt][1] * scale;
            sc[(r0 + 8) * 132 + c]     = acc[mt][nt][2] * scale;
            sc[(r0 + 8) * 132 + c + 1] = acc[mt][nt][3] * scale;
        }
    }
    __syncthreads();

#pragma unroll
    for (int j = 0; j < 4; j++) wa[warp * 128 + lane + 32 * j] = 0.0f;
    __syncwarp();

    for (int s = warp; s < 128; s += 8) {
        float x0 = sc[s * 132 + lane];
        float x1 = sc[s * 132 + lane + 32];
        float x2 = sc[s * 132 + lane + 64];
        float x3 = sc[s * 132 + lane + 96];
        float m = fmaxf(fmaxf(x0, x1), fmaxf(x2, x3));
#pragma unroll
        for (int o = 16; o; o >>= 1) m = fmaxf(m, __shfl_xor_sync(0xffffffffu, m, o));
        float e0 = expf(x0 - m), e1 = expf(x1 - m), e2 = expf(x2 - m), e3 = expf(x3 - m);
        float smm = e0 + e1 + e2 + e3;
#pragma unroll
        for (int o = 16; o; o >>= 1) smm += __shfl_xor_sync(0xffffffffu, smm, o);
        float inv = 1.0f / smm;
        wa[warp * 128 + lane]      += e0 * inv;
        wa[warp * 128 + lane + 32] += e1 * inv;
        wa[warp * 128 + lane + 64] += e2 * inv;
        wa[warp * 128 + lane + 96] += e3 * inv;
    }
    __syncthreads();
    if (warp == 0) {
#pragma unroll
        for (int j = 0; j < 4; j++) {
            int c = lane + 32 * j;
            float s = 0.f;
#pragma unroll
            for (int w = 0; w < 8; w++) s += wa[w * 128 + c];
            wa[c] = s;
        }
    }
    __syncthreads();

    float a = 0.0f;
    if (tid < 96) {
        const float* v = qkv + (long)b * SS * 2304 + 1536 + h * 96 + tid;
#pragma unroll 8
        for (int k = 0; k < 128; k++) a = fmaf(wa[k], v[(long)k * 2304], a);
        a *= (1.0f / 128.0f);
    }
    __syncthreads();
    if (tid < 96) sc[tid] = a;
    __syncthreads();
    if (tid < 48) {
        uint32_t hw, lw;
        split2(sc[2 * tid], sc[2 * tid + 1], hw, lw);
        long w = (long)b * 384 + h * 48 + tid;
        abh[w] = hw;
        abl[w] = lw;
    }
}

// ---------------- split-K reduction (pairwise; optional split output) ----------------
__global__ void reduce_k(const float* __restrict__ part, int Z, long stride,
                         const float* __restrict__ bias, int N,
                         float* __restrict__ C, uint32_t* __restrict__ Ch,
                         uint32_t* __restrict__ Cl, int totalPairs)
{
    int p = blockIdx.x * blockDim.x + threadIdx.x;
    if (p < totalPairs) {
        int i0 = 2 * p;
        float s0 = 0.f, s1 = 0.f;
        for (int zz = 0; zz < Z; zz++) {
            s0 += part[(long)zz * stride + i0];
            s1 += part[(long)zz * stride + i0 + 1];
        }
        s0 += bias[i0 % N];
        s1 += bias[(i0 + 1) % N];
        C[i0] = s0; C[i0 + 1] = s1;
        if (Ch) {
            uint32_t hw, lw;
            split2(s0, s1, hw, lw);
            Ch[p] = hw; Cl[p] = lw;
        }
    }
}

// ---------------- fused split-K reduce + LayerNorm + GELU (+ optional split) ----------------
// one block per row; part[z][row*N + i]
__global__ void redln_k(const float* __restrict__ part, int Z, long stride,
                        const float* __restrict__ bias,
                        const float* __restrict__ gm, const float* __restrict__ be,
                        float* __restrict__ outF,
                        uint32_t* __restrict__ oh, uint32_t* __restrict__ ol, int N)
{
    __shared__ float buf[1536];
    __shared__ float rs[8], rs2[8], sm_mean, sm_rstd;
    int row = blockIdx.x;
    int tid = threadIdx.x, warp = tid >> 5, lane = tid & 31;
    const float* pb = part + (long)row * N;

    float s = 0.f, s2 = 0.f;
    for (int i = tid; i < N; i += blockDim.x) {
        float v = 0.f;
        for (int zz = 0; zz < Z; zz++) v += pb[(long)zz * stride + i];
        v += bias[i];
        buf[i] = v;
        s += v; s2 += v * v;
    }
#pragma unroll
    for (int o = 16; o; o >>= 1) { s += __shfl_xor_sync(0xffffffffu, s, o); s2 += __shfl_xor_sync(0xffffffffu, s2, o); }
    if (lane == 0) { rs[warp] = s; rs2[warp] = s2; }
    __syncthreads();
    if (tid == 0) {
        float S = 0.f, S2 = 0.f;
        for (int w = 0; w < 8; w++) { S += rs[w]; S2 += rs2[w]; }
        float mean = S / N;
        float var = S2 / N - mean * mean;
        sm_mean = mean;
        sm_rstd = rsqrtf(var + 1e-5f);
    }
    __syncthreads();
    float mean = sm_mean, rstd = sm_rstd;
    int half = N >> 1;
    for (int p = tid; p < half; p += blockDim.x) {
        float v0 = (buf[2 * p] - mean) * rstd * gm[2 * p] + be[2 * p];
        float v1 = (buf[2 * p + 1] - mean) * rstd * gm[2 * p + 1] + be[2 * p + 1];
        v0 = 0.5f * v0 * (1.0f + erff(v0 * 0.70710678118654752f));
        v1 = 0.5f * v1 * (1.0f + erff(v1 * 0.70710678118654752f));
        outF[(long)row * N + 2 * p] = v0;
        outF[(long)row * N + 2 * p + 1] = v1;
        if (oh) {
            uint32_t hw, lw;
            split2(v0, v1, hw, lw);
            oh[(long)row * half + p] = hw;
            ol[(long)row * half + p] = lw;
        }
    }
}

// ---------------- warp dot helper ----------------
__device__ __forceinline__ float warp_dot(const float* a, const float* b, int n, int lane)
{
    float s = 0.f;
    for (int i = lane; i < n; i += 32) s = fmaf(a[i], b[i], s);
#pragma unroll
    for (int o = 16; o; o >>= 1) s += __shfl_xor_sync(0xffffffffu, s, o);
    return s;
}

// ---------------- small 5-way head (domain logits) ----------------
__global__ void head5_kernel(const float* __restrict__ in, int Kin,
                             const float* __restrict__ w, const float* __restrict__ bias,
                             float* __restrict__ out)
{
    int b = blockIdx.x, warp = threadIdx.x >> 5, lane = threadIdx.x & 31;
    if (warp < 5) {
        float s = warp_dot(in + (long)b * Kin, w + (long)warp * Kin, Kin, lane);
        if (lane == 0) out[b * 5 + warp] = s + bias[warp];
    }
}

// ---------------- gating softmax + top-2 + expert mix ----------------
__global__ void gate_kernel(const float* __restrict__ r1o,
                            const float* __restrict__ w_r2, const float* __restrict__ b_r2,
                            const float* __restrict__ hs,
                            const float* __restrict__ w_e, const float* __restrict__ b_e,
                            float* __restrict__ out)
{
    __shared__ float gl[5], ae[10];
    int b = blockIdx.x, tid = threadIdx.x, warp = tid >> 5, lane = tid & 31;

    if (warp < 5) {
        float s = warp_dot(r1o + (long)b * 384, w_r2 + (long)warp * 384, 384, lane);
        if (lane == 0) gl[warp] = s + b_r2[warp];
    }
    const float* cls = hs + (long)b * SS * HH;
    for (int idx = warp; idx < 10; idx += 8) {
        float s = warp_dot(cls, w_e + (long)idx * HH, HH, lane);
        if (lane == 0) ae[idx] = s + b_e[idx];
    }
    __syncthreads();

    if (tid == 0) {
        float m = gl[0];
        for (int j = 1; j < 5; j++) m = fmaxf(m, gl[j]);
        float e[5], sum = 0.f;
        for (int j = 0; j < 5; j++) { e[j] = expf(gl[j] - m); sum += e[j]; }
        float p[5];
        for (int j = 0; j < 5; j++) { p[j] = e[j] / sum; out[512 + b * 5 + j] = p[j]; }
        int i1 = 0;
        for (int j = 1; j < 5; j++) if (p[j] > p[i1]) i1 = j;
        int i2 = -1;
        for (int j = 0; j < 5; j++) if (j != i1 && (i2 < 0 || p[j] > p[i2])) i2 = j;
        float ps = p[i1] + p[i2];
        float w1 = p[i1] / ps, w2 = p[i2] / ps;
        for (int ee = 0; ee < 5; ee++) {
            bool sel = (ee == i1) || (ee == i2);
            out[1792 + b * 10 + ee * 2 + 0] = sel ? ae[ee * 2 + 0] : 0.0f;
            out[1792 + b * 10 + ee * 2 + 1] = sel ? ae[ee * 2 + 1] : 0.0f;
        }
        out[b * 2 + 0] = w1 * ae[i1 * 2 + 0] + w2 * ae[i2 * 2 + 0];
        out[b * 2 + 1] = w1 * ae[i1 * 2 + 1] + w2 * ae[i2 * 2 + 1];
    }
}

// ---------------- host launcher ----------------
extern "C" void kernel_launch(void* const* d_in, const int* in_sizes, int n_in,
                              void* d_out, int out_size)
{
    const float* hs    = (const float*)d_in[0];
    const float* w_qkv = (const float*)d_in[1];
    const float* b_qkv = (const float*)d_in[2];
    const float* w_out = (const float*)d_in[3];
    const float* b_out = (const float*)d_in[4];
    const float* w_f1  = (const float*)d_in[5];
    const float* b_f1  = (const float*)d_in[6];
    const float* gf1   = (const float*)d_in[7];
    const float* bef1  = (const float*)d_in[8];
    const float* w_f2  = (const float*)d_in[9];
    const float* b_f2  = (const float*)d_in[10];
    const float* gf2   = (const float*)d_in[11];
    const float* bef2  = (const float*)d_in[12];
    const float* w_c   = (const float*)d_in[13];
    const float* b_c   = (const float*)d_in[14];
    const float* gc    = (const float*)d_in[15];
    const float* bec   = (const float*)d_in[16];
    const float* w_r1  = (const float*)d_in[17];
    const float* b_r1  = (const float*)d_in[18];
    const float* gr1   = (const float*)d_in[19];
    const float* ber1  = (const float*)d_in[20];
    const float* w_r2  = (const float*)d_in[21];
    const float* b_r2  = (const float*)d_in[22];
    const float* w_d1  = (const float*)d_in[23];
    const float* b_d1  = (const float*)d_in[24];
    const float* gd1   = (const float*)d_in[25];
    const float* bed1  = (const float*)d_in[26];
    const float* w_d2  = (const float*)d_in[27];
    const float* b_d2  = (const float*)d_in[28];
    const float* w_e   = (const float*)d_in[29];
    const float* b_e   = (const float*)d_in[30];
    float* out = (float*)d_out;

    float *qkv, *seqr, *bufA, *bufB, *d1o, *part;
    cudaGetSymbolAddress((void**)&qkv,   g_qkv);
    cudaGetSymbolAddress((void**)&seqr,  g_seqr);
    cudaGetSymbolAddress((void**)&bufA,  g_bufA);
    cudaGetSymbolAddress((void**)&bufB,  g_bufB);
    cudaGetSymbolAddress((void**)&d1o,   g_d1o);
    cudaGetSymbolAddress((void**)&part,  g_part);

    uint32_t *hsh, *hsl, *qkh, *qkl, *outh, *outl, *f1h, *f1l, *f2h, *f2l;
    uint32_t *ch, *cl, *r1h, *r1l, *d1h, *d1l, *abh, *abl, *sqh, *sql;
    uint32_t *a1h, *a1l, *a2h, *a2l;
    cudaGetSymbolAddress((void**)&hsh, g_hs_h);   cudaGetSymbolAddress((void**)&hsl, g_hs_l);
    cudaGetSymbolAddress((void**)&qkh, g_wqkv_h); cudaGetSymbolAddress((void**)&qkl, g_wqkv_l);
    cudaGetSymbolAddress((void**)&outh, g_wout_h); cudaGetSymbolAddress((void**)&outl, g_wout_l);
    cudaGetSymbolAddress((void**)&f1h, g_wf1_h);  cudaGetSymbolAddress((void**)&f1l, g_wf1_l);
    cudaGetSymbolAddress((void**)&f2h, g_wf2_h);  cudaGetSymbolAddress((void**)&f2l, g_wf2_l);
    cudaGetSymbolAddress((void**)&ch,  g_wc_h);   cudaGetSymbolAddress((void**)&cl,  g_wc_l);
    cudaGetSymbolAddress((void**)&r1h, g_wr1_h);  cudaGetSymbolAddress((void**)&r1l, g_wr1_l);
    cudaGetSymbolAddress((void**)&d1h, g_wd1_h);  cudaGetSymbolAddress((void**)&d1l, g_wd1_l);
    cudaGetSymbolAddress((void**)&abh, g_abar_h); cudaGetSymbolAddress((void**)&abl, g_abar_l);
    cudaGetSymbolAddress((void**)&sqh, g_seqr_h); cudaGetSymbolAddress((void**)&sql, g_seqr_l);
    cudaGetSymbolAddress((void**)&a1h, g_act1_h); cudaGetSymbolAddress((void**)&a1l, g_act1_l);
    cudaGetSymbolAddress((void**)&a2h, g_act2_h); cudaGetSymbolAddress((void**)&a2l, g_act2_l);

    cudaFuncSetAttribute(gemm_sp_k,    cudaFuncAttributeMaxDynamicSharedMemorySize, GEMM_SMEM);
    cudaFuncSetAttribute(attn_fused_k, cudaFuncAttributeMaxDynamicSharedMemorySize, ATTN_SMEM);

    auto split = [&](const float* in, int lda, int M, int K, uint32_t* oh, uint32_t* ol) {
        long t4 = (long)M * K / 4;
        presplit_k<<<(unsigned)((t4 + 255) / 256), 256>>>(in, lda, K, oh, ol, t4);
    };

    // 0-2: pre-split hs / w_qkv / w_d1  (qkv at launch idx 3 for ncu capture)
    split(hs,    768, 32768, 768, hsh, hsl);          // 0
    split(w_qkv, 768, 2304,  768, qkh, qkl);          // 1
    split(w_d1,  768, 384,   768, d1h, d1l);          // 2

    // 3: qkv = hs @ w_qkv.T + b_qkv
    gemm_sp_k<<<dim3(18, 256, 1), 256, GEMM_SMEM>>>(
        hsh, hsl, 384, qkh, qkl, 384, 0, b_qkv, qkv, 2304, 0, 768, 1);

    // remaining weight pre-splits
    split(w_out, 768,  768,  768,  outh, outl);
    split(w_f1,  768,  1536, 768,  f1h,  f1l);
    split(w_f2,  1536, 1536, 1536, f2h,  f2l);
    split(w_c,   1536, 768,  1536, ch,   cl);
    split(w_r1,  768,  384,  768,  r1h,  r1l);

    // split-K GEMM (Kc = 128 -> kchunkw = 64)
    auto gemm_part = [&](const uint32_t* Ah, const uint32_t* Al, int ldaw,
                         const uint32_t* Wh, const uint32_t* Wl, int ldww,
                         int N, int K) {
        int Z = K / 128;
        dim3 grid(N / 128, BB / 128, Z);
        gemm_sp_k<<<grid, 256, GEMM_SMEM>>>(
            Ah, Al, ldaw, Wh, Wl, ldww, 64, nullptr, part, N, (long)BB * N, 128, Z);
        return Z;
    };

    // fused GEMM -> (reduce + LN + GELU + split)
    auto gemm_ln = [&](const uint32_t* Ah, const uint32_t* Al, int ldaw,
                       const uint32_t* Wh, const uint32_t* Wl, int ldww,
                       const float* bias, const float* gm, const float* be,
                       float* outF, uint32_t* oh, uint32_t* ol, int N, int K) {
        int Z = gemm_part(Ah, Al, ldaw, Wh, Wl, ldww, N, K);
        redln_k<<<BB, 256>>>(part, Z, (long)BB * N, bias, gm, be, outF, oh, ol, N);
    };

    // domain path
    gemm_ln(hsh, hsl, SS * 384, d1h, d1l, 384, b_d1, gd1, bed1, d1o, nullptr, nullptr, 384, 768);
    head5_kernel<<<BB, 160>>>(d1o, 384, w_d2, b_d2, out + 4352);

    // fused attention -> abar (split)
    attn_fused_k<<<BB * NHH, 256, ATTN_SMEM>>>(qkv, abh, abl);

    // seq_repr = abar @ w_out.T + b_out  (no LN -> plain reduce with split out)
    {
        int Z = gemm_part(abh, abl, 384, outh, outl, 384, 768, 768);
        int pairs = BB * 768 / 2;
        reduce_k<<<(pairs + 255) / 256, 256>>>(part, Z, (long)BB * 768, b_out, 768,
                                               seqr, sqh, sql, pairs);
    }

    // f1 -> f2 -> ctx -> r1 chain (all fused reduce+LN+GELU)
    gemm_ln(sqh, sql, 384, f1h, f1l, 384, b_f1, gf1, bef1, bufA, a1h, a1l, 1536, 768);
    gemm_ln(a1h, a1l, 768, f2h, f2l, 768, b_f2, gf2, bef2, bufA, a2h, a2l, 1536, 1536);
    gemm_ln(a2h, a2l, 768, ch, cl, 768, b_c, gc, bec, bufA, a1h, a1l, 768, 1536);
    gemm_ln(a1h, a1l, 384, r1h, r1l, 384, b_r1, gr1, ber1, bufB, nullptr, nullptr, 384, 768);

    // gating softmax + top-2 + expert logits / final logits
    gate_kernel<<<BB, 256>>>(bufB, w_r2, b_r2, hs, w_e, b_e, out);

    (void)in_sizes; (void)n_in; (void)out_size;
}